// round 8
// baseline (speedup 1.0000x reference)
#include <cuda_runtime.h>
#include <cuda_bf16.h>
#include <cstdint>
#include <math.h>

#define B_     16
#define LQ     4096
#define LK     77
#define DMODEL 512
#define DCOND  768
#define NH     8
#define HD     64
#define INNER  512   // NH*HD
#define MKV    1232  // B_*LK
#define MKVP   1280  // padded to 128

// Scratch (allocation-free rule: __device__ globals; zero-initialized)
__device__ float g_Q[(size_t)B_ * LQ * INNER];
__device__ float g_KV[(size_t)MKVP * 1024];          // K cols 0..511, V 512..1023
__device__ int8_t g_xq0[(size_t)B_ * LQ * DMODEL];
__device__ int8_t g_xq1[(size_t)B_ * LQ * DMODEL];
__device__ int8_t g_aq0[(size_t)B_ * LQ * INNER];
__device__ int8_t g_aq1[(size_t)B_ * LQ * INNER];
__device__ int8_t g_wqq0[DMODEL * INNER];
__device__ int8_t g_wqq1[DMODEL * INNER];
__device__ int8_t g_woq0[DMODEL * INNER];
__device__ int8_t g_woq1[DMODEL * INNER];
__device__ int8_t g_cq0[MKVP * DCOND];               // rows >= 1232 stay 0
__device__ int8_t g_cq1[MKVP * DCOND];
__device__ int8_t g_wkvq0[2 * INNER * DCOND];        // [w_k ; w_v]
__device__ int8_t g_wkvq1[2 * INNER * DCOND];

// ===========================================================================
// Helpers (base PTX only)
// ===========================================================================
__device__ __forceinline__ uint32_t smem_u32(const void* p) {
    uint32_t a;
    asm("{ .reg .u64 t; cvta.to.shared.u64 t, %1; cvt.u32.u64 %0, t; }" : "=r"(a) : "l"(p));
    return a;
}
__device__ __forceinline__ uint32_t swz128(uint32_t off) { return off ^ ((off >> 3) & 0x70); }

__device__ __forceinline__ void ldmatrix_x4(uint32_t* r, uint32_t addr) {
    asm volatile("ldmatrix.sync.aligned.m8n8.x4.shared.b16 {%0,%1,%2,%3}, [%4];"
        : "=r"(r[0]), "=r"(r[1]), "=r"(r[2]), "=r"(r[3]) : "r"(addr));
}
__device__ __forceinline__ void ldmatrix_x2(uint32_t* r, uint32_t addr) {
    asm volatile("ldmatrix.sync.aligned.m8n8.x2.shared.b16 {%0,%1}, [%2];"
        : "=r"(r[0]), "=r"(r[1]) : "r"(addr));
}
// s8 IMMA: D[16x8] s32 (+)= A[16x32] s8 @ B[8x32]^T s8
__device__ __forceinline__ void mma_s8(int* d, const uint32_t* a, const uint32_t* b) {
    asm volatile("mma.sync.aligned.m16n8k32.row.col.s32.s8.s8.s32 "
        "{%0,%1,%2,%3}, {%4,%5,%6,%7}, {%8,%9}, {%0,%1,%2,%3};"
        : "+r"(d[0]), "+r"(d[1]), "+r"(d[2]), "+r"(d[3])
        : "r"(a[0]), "r"(a[1]), "r"(a[2]), "r"(a[3]), "r"(b[0]), "r"(b[1]));
}
__device__ __forceinline__ void cp_async16(uint32_t dst, const void* src) {
    asm volatile("cp.async.cg.shared.global [%0], [%1], 16;" :: "r"(dst), "l"(src));
}
#define CP_COMMIT() asm volatile("cp.async.commit_group;" ::: "memory")
#define CP_WAIT2()  asm volatile("cp.async.wait_group 2;" ::: "memory")

__device__ __forceinline__ void fma2(uint64_t& d, uint64_t a, uint64_t b) {
    asm("fma.rn.f32x2 %0, %1, %2, %0;" : "+l"(d) : "l"(a), "l"(b));
}
__device__ __forceinline__ float hadd2(uint64_t v) {
    float lo, hi;
    asm("mov.b64 {%0,%1}, %2;" : "=f"(lo), "=f"(hi) : "l"(v));
    return lo + hi;
}
__device__ __forceinline__ int clamp127(int v) {
    return v < -127 ? -127 : (v > 127 ? 127 : v);
}

// ===========================================================================
// fp32 -> dual-level int8 quantization:  x ~= q0/s0 + q1/(s0*256)
// ===========================================================================
__global__ void cvt_q8(const float4* __restrict__ in, char4* __restrict__ q0,
                       char4* __restrict__ q1, int n4, float s0, float inv_s0, float s1)
{
    const int i = blockIdx.x * blockDim.x + threadIdx.x;
    if (i >= n4) return;
    const float4 v = in[i];
    int a0 = clamp127(__float2int_rn(v.x * s0));
    int a1 = clamp127(__float2int_rn(v.y * s0));
    int a2 = clamp127(__float2int_rn(v.z * s0));
    int a3 = clamp127(__float2int_rn(v.w * s0));
    int b0 = clamp127(__float2int_rn((v.x - a0 * inv_s0) * s1));
    int b1 = clamp127(__float2int_rn((v.y - a1 * inv_s0) * s1));
    int b2 = clamp127(__float2int_rn((v.z - a2 * inv_s0) * s1));
    int b3 = clamp127(__float2int_rn((v.w - a3 * inv_s0) * s1));
    q0[i] = make_char4((char)a0, (char)a1, (char)a2, (char)a3);
    q1[i] = make_char4((char)b0, (char)b1, (char)b2, (char)b3);
}

// ===========================================================================
// IMMA GEMM on dual-level int8:
//   C = f00*A0B0 + fx*(A0B1 + A1B0) + f11*A1B1    (fx valid since S1/S0 = 256
//   for both operands). 128x128 tile, K-chunk 64, 3-stage cp.async.
// 512 threads (16 warps 4x4), warp tile 32x32.
// smem/stage 32KB: A tile 128 rows x [A0 64B | A1 64B] (SW128), B same @16K.
// ===========================================================================
#define GM_SMEM (3 * 32768)

template <int KDIM, int LDC>
__global__ void __launch_bounds__(512, 1)
gemm_s8(const int8_t* __restrict__ A0, const int8_t* __restrict__ A1,
        const int8_t* __restrict__ B0, const int8_t* __restrict__ B1,
        float* __restrict__ C, float f00, float fx, float f11)
{
    constexpr int NCHUNK = KDIM / 64;
    extern __shared__ char sm[];
    const uint32_t base = smem_u32(sm);
    const int tid  = threadIdx.x;
    const int wid  = tid >> 5;
    const int lane = tid & 31;
    const int wm   = wid & 3;    // 4 m-blocks of 32
    const int wn   = wid >> 2;   // 4 n-blocks of 32

    const int m0 = blockIdx.x * 128;
    const int n0 = blockIdx.y * 128;
    const int8_t* A0c = A0 + (size_t)m0 * KDIM;
    const int8_t* A1c = A1 + (size_t)m0 * KDIM;
    const int8_t* B0c = B0 + (size_t)n0 * KDIM;
    const int8_t* B1c = B1 + (size_t)n0 * KDIM;

    float acc[2][4][4];
#pragma unroll
    for (int mt = 0; mt < 2; ++mt)
#pragma unroll
        for (int nt = 0; nt < 4; ++nt)
#pragma unroll
            for (int q = 0; q < 4; ++q) acc[mt][nt][q] = 0.f;

    // unswizzled fragment base offsets (bytes within tile)
    uint32_t aBase[2], bBase[4];
#pragma unroll
    for (int mt = 0; mt < 2; ++mt)
        aBase[mt] = (uint32_t)((wm * 32 + mt * 16 + (lane & 15)) * 128 + (lane >> 4) * 16);
#pragma unroll
    for (int nt = 0; nt < 4; ++nt)
        bBase[nt] = (uint32_t)((wn * 32 + nt * 8 + (lane & 7)) * 128 + ((lane >> 3) & 1) * 16);

    // stage one k64 chunk: A(0|1) 1024 chunks + B 1024 chunks of 16B
    auto issue_chunk = [&](int c, int buf) {
        const int kc = c * 64;
        const uint32_t tb = base + buf * 32768;
#pragma unroll
        for (int i = 0; i < 2; ++i) {
            const int idx  = i * 512 + tid;        // 0..1023
            const int row  = idx >> 3;
            const int part = (idx >> 2) & 1;
            const int c16  = idx & 3;
            const uint32_t so = swz128((uint32_t)(row * 128 + part * 64 + c16 * 16));
            const size_t go = (size_t)row * KDIM + kc + c16 * 16;
            cp_async16(tb + so,         (part ? A1c : A0c) + go);
            cp_async16(tb + 16384 + so, (part ? B1c : B0c) + go);
        }
    };

    issue_chunk(0, 0); CP_COMMIT();
    issue_chunk(1, 1); CP_COMMIT();
    issue_chunk(2, 2); CP_COMMIT();

    for (int c = 0; c < NCHUNK; ++c) {
        const int buf = c % 3;
        CP_WAIT2();
        __syncthreads();

        const uint32_t bufA = base + buf * 32768;
        const uint32_t bufB = bufA + 16384;
#pragma unroll
        for (int s = 0; s < 2; ++s) {          // 2 k32 steps
            const uint32_t kb = s * 32;
            uint32_t a0f[2][4], a1f[2][4], b0f[4][2], b1f[4][2];
#pragma unroll
            for (int mt = 0; mt < 2; ++mt) {
                const uint32_t o0 = aBase[mt] + kb;
                ldmatrix_x4(a0f[mt], bufA + (o0 ^ ((o0 >> 3) & 0x70)));
                const uint32_t o1 = o0 + 64;
                ldmatrix_x4(a1f[mt], bufA + (o1 ^ ((o1 >> 3) & 0x70)));
            }
#pragma unroll
            for (int nt = 0; nt < 4; ++nt) {
                const uint32_t o0 = bBase[nt] + kb;
                ldmatrix_x2(b0f[nt], bufB + (o0 ^ ((o0 >> 3) & 0x70)));
                const uint32_t o1 = o0 + 64;
                ldmatrix_x2(b1f[nt], bufB + (o1 ^ ((o1 >> 3) & 0x70)));
            }
#pragma unroll
            for (int mt = 0; mt < 2; ++mt)
#pragma unroll
                for (int nt = 0; nt < 4; ++nt) {
                    int c00[4] = {0, 0, 0, 0};
                    int cx[4]  = {0, 0, 0, 0};
                    int c11[4] = {0, 0, 0, 0};
                    mma_s8(c00, a0f[mt], b0f[nt]);
                    mma_s8(cx,  a0f[mt], b1f[nt]);
                    mma_s8(cx,  a1f[mt], b0f[nt]);
                    mma_s8(c11, a1f[mt], b1f[nt]);
#pragma unroll
                    for (int q = 0; q < 4; ++q)
                        acc[mt][nt][q] += f00 * (float)c00[q] + fx * (float)cx[q]
                                        + f11 * (float)c11[q];
                }
        }
        __syncthreads();
        if (c + 3 < NCHUNK) issue_chunk(c + 3, buf);
        CP_COMMIT();
    }

#pragma unroll
    for (int mt = 0; mt < 2; ++mt) {
        const int r = m0 + wm * 32 + mt * 16 + (lane >> 2);
#pragma unroll
        for (int nt = 0; nt < 4; ++nt) {
            const int cc = n0 + wn * 32 + nt * 8 + (lane & 3) * 2;
            *(float2*)(C + (size_t)r * LDC + cc)       = make_float2(acc[mt][nt][0], acc[mt][nt][1]);
            *(float2*)(C + (size_t)(r + 8) * LDC + cc) = make_float2(acc[mt][nt][2], acc[mt][nt][3]);
        }
    }
}

// ===========================================================================
// Fused attention (K/V from g_KV stride 1024). Emits dual-int8 output
// (scales: s0=64, s1=16384) feeding the O-projection IMMA GEMM.
// ===========================================================================
#define KS_PITCH 66
#define VT_PITCH 82
#define ATT_VT_OFF  5084
#define ATT_SCR_OFF (ATT_VT_OFF + 64 * VT_PITCH)
#define ATT_SMEM    ((ATT_SCR_OFF + 8 * 640) * 4)

__global__ __launch_bounds__(256)
void attn_kernel(const float* __restrict__ Q, const float* __restrict__ KV,
                 int8_t* __restrict__ Oq0, int8_t* __restrict__ Oq1)
{
    extern __shared__ float smf[];
    float* ks  = smf;                  // [j][d] pitch 66
    float* vt  = smf + ATT_VT_OFF;     // [d][j] pitch 82
    float* scr = smf + ATT_SCR_OFF;

    const int tid = threadIdx.x;
    const int w   = tid >> 5;
    const int l   = tid & 31;
    const int bh  = blockIdx.y;
    const int b   = bh >> 3;
    const int h   = bh & 7;

    const float* kg = KV + (size_t)b * LK * 1024 + h * HD;
    const float* vg = kg + 512;
    for (int idx = tid; idx < LK * HD; idx += 256) {
        const int j = idx >> 6, d = idx & 63;
        ks[j * KS_PITCH + d] = kg[(size_t)j * 1024 + d];
        vt[d * VT_PITCH + j] = vg[(size_t)j * 1024 + d];
    }

    float* pw = scr + w * 640;
    const size_t qbase = ((size_t)b * LQ + blockIdx.x * 64 + w * 8) * INNER + h * HD;
#pragma unroll
    for (int qq = 0; qq < 8; ++qq) {
        const float2 qv = ((const float2*)(Q + qbase + (size_t)qq * INNER))[l];
        pw[qq * 80 + 2 * l]     = qv.x * 0.125f;
        pw[qq * 80 + 2 * l + 1] = qv.y * 0.125f;
    }
    __syncthreads();

    const bool v2 = (l < (LK - 64));
    const int  j2 = v2 ? (64 + l) : 64;
    uint64_t a0[8], a1[8], a2[8];
#pragma unroll
    for (int qq = 0; qq < 8; ++qq) { a0[qq] = 0; a1[qq] = 0; a2[qq] = 0; }

#pragma unroll 4
    for (int d = 0; d < 64; d += 2) {
        const uint64_t k0 = *(const uint64_t*)(ks + l * KS_PITCH + d);
        const uint64_t k1 = *(const uint64_t*)(ks + (l + 32) * KS_PITCH + d);
        const uint64_t k2 = *(const uint64_t*)(ks + j2 * KS_PITCH + d);
#pragma unroll
        for (int qq = 0; qq < 8; ++qq) {
            const uint64_t q2 = *(const uint64_t*)(pw + qq * 80 + d);
            fma2(a0[qq], q2, k0);
            fma2(a1[qq], q2, k1);
            fma2(a2[qq], q2, k2);
        }
    }
    __syncwarp();

    float rs[8];
#pragma unroll
    for (int qq = 0; qq < 8; ++qq) {
        const float s0 = hadd2(a0[qq]);
        const float s1 = hadd2(a1[qq]);
        const float s2v = hadd2(a2[qq]);
        const float s2 = v2 ? s2v : -1e30f;
        float m = fmaxf(s0, fmaxf(s1, s2));
#pragma unroll
        for (int o = 16; o; o >>= 1) m = fmaxf(m, __shfl_xor_sync(0xffffffffu, m, o));
        const float e0 = __expf(s0 - m);
        const float e1 = __expf(s1 - m);
        const float e2 = v2 ? __expf(s2 - m) : 0.f;
        float sum = e0 + e1 + e2;
#pragma unroll
        for (int o = 16; o; o >>= 1) sum += __shfl_xor_sync(0xffffffffu, sum, o);
        rs[qq] = 1.f / sum;
        pw[qq * 80 + l]      = e0;
        pw[qq * 80 + l + 32] = e1;
        if (v2) pw[qq * 80 + 64 + l] = e2;
    }
    __syncwarp();

    uint64_t px[8], py[8];
#pragma unroll
    for (int qq = 0; qq < 8; ++qq) { px[qq] = 0; py[qq] = 0; }

    const float* vr0 = vt + (2 * l) * VT_PITCH;
    const float* vr1 = vt + (2 * l + 1) * VT_PITCH;
#pragma unroll 2
    for (int jp = 0; jp < 76; jp += 2) {
        const uint64_t v0 = *(const uint64_t*)(vr0 + jp);
        const uint64_t v1 = *(const uint64_t*)(vr1 + jp);
#pragma unroll
        for (int qq = 0; qq < 8; ++qq) {
            const uint64_t p2 = *(const uint64_t*)(pw + qq * 80 + jp);
            fma2(px[qq], p2, v0);
            fma2(py[qq], p2, v1);
        }
    }
    const float v0r = vr0[76];
    const float v1r = vr1[76];

#pragma unroll
    for (int qq = 0; qq < 8; ++qq) {
        const float pr = pw[qq * 80 + 76];
        const float ox = (hadd2(px[qq]) + pr * v0r) * rs[qq];
        const float oy = (hadd2(py[qq]) + pr * v1r) * rs[qq];
        // dual-int8 quantization: s0 = 64, s1 = 16384
        const int qx0 = clamp127(__float2int_rn(ox * 64.f));
        const int qy0 = clamp127(__float2int_rn(oy * 64.f));
        const int qx1 = clamp127(__float2int_rn((ox - qx0 * 0.015625f) * 16384.f));
        const int qy1 = clamp127(__float2int_rn((oy - qy0 * 0.015625f) * 16384.f));
        const size_t off = qbase + (size_t)qq * INNER + 2 * l;
        *(short*)(Oq0 + off) = (short)((qx0 & 0xFF) | ((qy0 & 0xFF) << 8));
        *(short*)(Oq1 + off) = (short)((qx1 & 0xFF) | ((qy1 & 0xFF) << 8));
    }
}

// ===========================================================================
extern "C" void kernel_launch(void* const* d_in, const int* in_sizes, int n_in,
                              void* d_out, int out_size)
{
    (void)in_sizes; (void)n_in; (void)out_size;
    const float* x    = (const float*)d_in[0];
    const float* cond = (const float*)d_in[1];
    const float* w_q  = (const float*)d_in[2];
    const float* w_k  = (const float*)d_in[3];
    const float* w_v  = (const float*)d_in[4];
    const float* w_o  = (const float*)d_in[5];
    float* out = (float*)d_out;

    float *Qb, *KVb;
    int8_t *xq0, *xq1, *aq0, *aq1, *wqq0, *wqq1, *woq0, *woq1, *cq0, *cq1, *wkq0, *wkq1;
    cudaGetSymbolAddress((void**)&Qb, g_Q);
    cudaGetSymbolAddress((void**)&KVb, g_KV);
    cudaGetSymbolAddress((void**)&xq0, g_xq0);   cudaGetSymbolAddress((void**)&xq1, g_xq1);
    cudaGetSymbolAddress((void**)&aq0, g_aq0);   cudaGetSymbolAddress((void**)&aq1, g_aq1);
    cudaGetSymbolAddress((void**)&wqq0, g_wqq0); cudaGetSymbolAddress((void**)&wqq1, g_wqq1);
    cudaGetSymbolAddress((void**)&woq0, g_woq0); cudaGetSymbolAddress((void**)&woq1, g_woq1);
    cudaGetSymbolAddress((void**)&cq0, g_cq0);   cudaGetSymbolAddress((void**)&cq1, g_cq1);
    cudaGetSymbolAddress((void**)&wkq0, g_wkvq0); cudaGetSymbolAddress((void**)&wkq1, g_wkvq1);

    cudaFuncSetAttribute(gemm_s8<512, 512>,  cudaFuncAttributeMaxDynamicSharedMemorySize, GM_SMEM);
    cudaFuncSetAttribute(gemm_s8<768, 1024>, cudaFuncAttributeMaxDynamicSharedMemorySize, GM_SMEM);
    cudaFuncSetAttribute(attn_kernel, cudaFuncAttributeMaxDynamicSharedMemorySize, ATT_SMEM);

    // Quantize (x/cond: s0=16, s1=4096; weights: s0=1024, s1=262144)
    const int XN4 = B_ * LQ * DMODEL / 4;
    const int WN4 = DMODEL * INNER / 4;
    const int CN4 = MKV * DCOND / 4;
    const int WKN4 = INNER * DCOND / 4;
    cvt_q8<<<(XN4 + 255) / 256, 256>>>((const float4*)x, (char4*)xq0, (char4*)xq1, XN4,
                                        16.f, 1.f / 16.f, 4096.f);
    cvt_q8<<<(WN4 + 255) / 256, 256>>>((const float4*)w_q, (char4*)wqq0, (char4*)wqq1, WN4,
                                        1024.f, 1.f / 1024.f, 262144.f);
    cvt_q8<<<(WN4 + 255) / 256, 256>>>((const float4*)w_o, (char4*)woq0, (char4*)woq1, WN4,
                                        1024.f, 1.f / 1024.f, 262144.f);
    cvt_q8<<<(CN4 + 255) / 256, 256>>>((const float4*)cond, (char4*)cq0, (char4*)cq1, CN4,
                                        16.f, 1.f / 16.f, 4096.f);
    cvt_q8<<<(WKN4 + 255) / 256, 256>>>((const float4*)w_k, (char4*)wkq0, (char4*)wkq1, WKN4,
                                        1024.f, 1.f / 1024.f, 262144.f);
    cvt_q8<<<(WKN4 + 255) / 256, 256>>>((const float4*)w_v,
        (char4*)(wkq0 + (size_t)INNER * DCOND), (char4*)(wkq1 + (size_t)INNER * DCOND), WKN4,
                                        1024.f, 1.f / 1024.f, 262144.f);

    // scale products: A(16,4096) x B(1024,262144)
    const float qf00 = 1.f / 16384.f, qfx = 1.f / 4194304.f, qf11 = 1.f / 1073741824.f;
    // A(64,16384) x B(1024,262144)
    const float of00 = 1.f / 65536.f, ofx = 1.f / 16777216.f, of11 = 2.3283064365386963e-10f;

    // K+V projection: [1280,768] @ [1024,768]^T -> g_KV (fp32)
    gemm_s8<768, 1024><<<dim3(MKVP / 128, 8), 512, GM_SMEM>>>(
        cq0, cq1, wkq0, wkq1, KVb, qf00, qfx, qf11);

    // Q projection: [65536,512] @ [512,512]^T -> g_Q (fp32)
    gemm_s8<512, 512><<<dim3(512, 4), 512, GM_SMEM>>>(
        xq0, xq1, wqq0, wqq1, Qb, qf00, qfx, qf11);

    // Fused attention -> dual-int8
    attn_kernel<<<dim3(LQ / 64, B_ * NH), 256, ATT_SMEM>>>(Qb, KVb, aq0, aq1);

    // Output projection: [65536,512] @ [512,512]^T -> out (fp32)
    gemm_s8<512, 512><<<dim3(512, 4), 512, GM_SMEM>>>(
        aq0, aq1, woq0, woq1, out, of00, ofx, of11);
}

// round 9
// speedup vs baseline: 3.0677x; 3.0677x over previous
#include <cuda_runtime.h>
#include <cuda_bf16.h>
#include <cstdint>
#include <math.h>

#define B_     16
#define LQ     4096
#define LK     77
#define DMODEL 512
#define DCOND  768
#define NH     8
#define HD     64
#define INNER  512   // NH*HD
#define MKV    1232  // B_*LK
#define MKVP   1280  // padded to 128

// Scratch (allocation-free rule: __device__ globals; zero-initialized)
__device__ __nv_bfloat16 g_xhi[(size_t)B_ * LQ * DMODEL];
__device__ __nv_bfloat16 g_xlo[(size_t)B_ * LQ * DMODEL];
__device__ __nv_bfloat16 g_qhi[(size_t)B_ * LQ * INNER];   // Q*0.125 split
__device__ __nv_bfloat16 g_qlo[(size_t)B_ * LQ * INNER];
__device__ __nv_bfloat16 g_ahi[(size_t)B_ * LQ * INNER];   // attention out split
__device__ __nv_bfloat16 g_alo[(size_t)B_ * LQ * INNER];
__device__ __nv_bfloat16 g_wqhi[DMODEL * INNER];
__device__ __nv_bfloat16 g_wqlo[DMODEL * INNER];
__device__ __nv_bfloat16 g_wohi[DMODEL * INNER];
__device__ __nv_bfloat16 g_wolo[DMODEL * INNER];
__device__ __nv_bfloat16 g_chi[MKVP * DCOND];              // cond split (pad rows 0)
__device__ __nv_bfloat16 g_clo[MKVP * DCOND];
__device__ __nv_bfloat16 g_wkvhi[2 * INNER * DCOND];       // [w_k ; w_v]
__device__ __nv_bfloat16 g_wkvlo[2 * INNER * DCOND];
__device__ __nv_bfloat16 g_kvhi[(size_t)MKVP * 1024];      // K cols 0..511, V 512..1023
__device__ __nv_bfloat16 g_kvlo[(size_t)MKVP * 1024];

// ===========================================================================
// Helpers (base PTX only)
// ===========================================================================
__device__ __forceinline__ uint32_t smem_u32(const void* p) {
    uint32_t a;
    asm("{ .reg .u64 t; cvta.to.shared.u64 t, %1; cvt.u32.u64 %0, t; }" : "=r"(a) : "l"(p));
    return a;
}
__device__ __forceinline__ uint32_t swz128(uint32_t off) { return off ^ ((off >> 3) & 0x70); }

__device__ __forceinline__ void ldmatrix_x4(uint32_t* r, uint32_t addr) {
    asm volatile("ldmatrix.sync.aligned.m8n8.x4.shared.b16 {%0,%1,%2,%3}, [%4];"
        : "=r"(r[0]), "=r"(r[1]), "=r"(r[2]), "=r"(r[3]) : "r"(addr));
}
__device__ __forceinline__ void ldmatrix_x2(uint32_t* r, uint32_t addr) {
    asm volatile("ldmatrix.sync.aligned.m8n8.x2.shared.b16 {%0,%1}, [%2];"
        : "=r"(r[0]), "=r"(r[1]) : "r"(addr));
}
__device__ __forceinline__ void mma16816(float* d, const uint32_t* a, const uint32_t* b) {
    asm volatile("mma.sync.aligned.m16n8k16.row.col.f32.bf16.bf16.f32 "
        "{%0,%1,%2,%3}, {%4,%5,%6,%7}, {%8,%9}, {%0,%1,%2,%3};"
        : "+f"(d[0]), "+f"(d[1]), "+f"(d[2]), "+f"(d[3])
        : "r"(a[0]), "r"(a[1]), "r"(a[2]), "r"(a[3]), "r"(b[0]), "r"(b[1]));
}
__device__ __forceinline__ void cp_async16(uint32_t dst, const void* src) {
    asm volatile("cp.async.cg.shared.global [%0], [%1], 16;" :: "r"(dst), "l"(src));
}
#define CP_COMMIT() asm volatile("cp.async.commit_group;" ::: "memory")
#define CP_WAIT2()  asm volatile("cp.async.wait_group 2;" ::: "memory")
#define CP_WAIT0()  asm volatile("cp.async.wait_group 0;" ::: "memory")

// split two floats into packed bf16x2 hi + residual lo
__device__ __forceinline__ void split2(float x, float y, uint32_t& hi, uint32_t& lo) {
    __nv_bfloat16 hx = __float2bfloat16_rn(x), hy = __float2bfloat16_rn(y);
    __nv_bfloat16 lx = __float2bfloat16_rn(x - __bfloat162float(hx));
    __nv_bfloat16 ly = __float2bfloat16_rn(y - __bfloat162float(hy));
    hi = (uint32_t)__bfloat16_as_ushort(hx) | ((uint32_t)__bfloat16_as_ushort(hy) << 16);
    lo = (uint32_t)__bfloat16_as_ushort(lx) | ((uint32_t)__bfloat16_as_ushort(ly) << 16);
}

__global__ void cvt_split(const float4* __restrict__ in, uint2* __restrict__ hi,
                          uint2* __restrict__ lo, int n4)
{
    const int i = blockIdx.x * blockDim.x + threadIdx.x;
    if (i >= n4) return;
    const float4 v = in[i];
    uint32_t h01, h23, l01, l23;
    split2(v.x, v.y, h01, l01);
    split2(v.z, v.w, h23, l23);
    hi[i] = make_uint2(h01, h23);
    lo[i] = make_uint2(l01, l23);
}

// ===========================================================================
// HMMA GEMM on pre-split bf16: C = (Ah+Al)(Bh+Bl)^T ≈ AhBh + AhBl + AlBh.
// 128x128 tile, K-chunk 64, 3-stage cp.async, 512 thr (16 warps 4x4), 32x32 warp.
// SPLIT=true: write premul-scaled bf16 hi/lo outputs instead of fp32.
// ===========================================================================
#define GM_SMEM (3 * 65536)

template <int KDIM, int LDC, bool SPLIT>
__global__ void __launch_bounds__(512, 1)
gemm_bf16(const __nv_bfloat16* __restrict__ Ah, const __nv_bfloat16* __restrict__ Al,
          const __nv_bfloat16* __restrict__ Bh, const __nv_bfloat16* __restrict__ Bl,
          float* __restrict__ C, __nv_bfloat16* __restrict__ Oh,
          __nv_bfloat16* __restrict__ Ol, float premul)
{
    constexpr int NCHUNK = KDIM / 64;
    extern __shared__ char sm[];
    const uint32_t base = smem_u32(sm);
    const int tid  = threadIdx.x;
    const int wid  = tid >> 5;
    const int lane = tid & 31;
    const int wm   = wid & 3;
    const int wn   = wid >> 2;

    const int m0 = blockIdx.x * 128;
    const int n0 = blockIdx.y * 128;
    const __nv_bfloat16* Ah0 = Ah + (size_t)m0 * KDIM;
    const __nv_bfloat16* Al0 = Al + (size_t)m0 * KDIM;
    const __nv_bfloat16* Bh0 = Bh + (size_t)n0 * KDIM;
    const __nv_bfloat16* Bl0 = Bl + (size_t)n0 * KDIM;

    float acc[2][4][4];
#pragma unroll
    for (int mt = 0; mt < 2; ++mt)
#pragma unroll
        for (int nt = 0; nt < 4; ++nt)
#pragma unroll
            for (int q = 0; q < 4; ++q) acc[mt][nt][q] = 0.f;

    uint32_t aRow0[2], bRow0[4];
#pragma unroll
    for (int mt = 0; mt < 2; ++mt)
        aRow0[mt] = (uint32_t)((wm * 32 + mt * 16 + (lane & 15)) * 128 + (lane >> 4) * 16);
#pragma unroll
    for (int nt = 0; nt < 4; ++nt)
        bRow0[nt] = (uint32_t)((wn * 32 + nt * 8 + (lane & 7)) * 128 + ((lane >> 3) & 1) * 16);

    auto issue_chunk = [&](int c, int buf) {
        const int kc = c * 64;
        const uint32_t tb = base + buf * 65536;
#pragma unroll
        for (int i = 0; i < 2; ++i) {
            const int idx  = i * 512 + tid;
            const int row  = idx >> 3;
            const int c16  = idx & 7;
            const uint32_t so = swz128((uint32_t)(row * 128 + c16 * 16));
            const size_t go = (size_t)row * KDIM + kc + c16 * 8;
            cp_async16(tb + so,         Ah0 + go);
            cp_async16(tb + 16384 + so, Al0 + go);
            cp_async16(tb + 32768 + so, Bh0 + go);
            cp_async16(tb + 49152 + so, Bl0 + go);
        }
    };

    issue_chunk(0, 0); CP_COMMIT();
    issue_chunk(1, 1); CP_COMMIT();
    issue_chunk(2, 2); CP_COMMIT();

    for (int c = 0; c < NCHUNK; ++c) {
        const int buf = c % 3;
        CP_WAIT2();
        __syncthreads();

        const uint32_t bufA = base + buf * 65536;
        const uint32_t bufB = bufA + 32768;
#pragma unroll
        for (int kb = 0; kb < 4; ++kb) {
            const uint32_t kbyte = kb * 32;
            uint32_t Ahf[2][4], Alf[2][4], Bhf[4][2], Blf[4][2];
#pragma unroll
            for (int mt = 0; mt < 2; ++mt) {
                const uint32_t off = aRow0[mt] + kbyte;
                const uint32_t so  = off ^ ((off >> 3) & 0x70);
                ldmatrix_x4(Ahf[mt], bufA + so);
                ldmatrix_x4(Alf[mt], bufA + 16384 + so);
            }
#pragma unroll
            for (int nt = 0; nt < 4; ++nt) {
                const uint32_t off = bRow0[nt] + kbyte;
                const uint32_t so  = off ^ ((off >> 3) & 0x70);
                ldmatrix_x2(Bhf[nt], bufB + so);
                ldmatrix_x2(Blf[nt], bufB + 16384 + so);
            }
#pragma unroll
            for (int mt = 0; mt < 2; ++mt)
#pragma unroll
                for (int nt = 0; nt < 4; ++nt)
                    mma16816(acc[mt][nt], Ahf[mt], Bhf[nt]);
#pragma unroll
            for (int mt = 0; mt < 2; ++mt)
#pragma unroll
                for (int nt = 0; nt < 4; ++nt)
                    mma16816(acc[mt][nt], Ahf[mt], Blf[nt]);
#pragma unroll
            for (int mt = 0; mt < 2; ++mt)
#pragma unroll
                for (int nt = 0; nt < 4; ++nt)
                    mma16816(acc[mt][nt], Alf[mt], Bhf[nt]);
        }
        __syncthreads();
        if (c + 3 < NCHUNK) issue_chunk(c + 3, buf);
        CP_COMMIT();
    }

#pragma unroll
    for (int mt = 0; mt < 2; ++mt) {
        const int r = m0 + wm * 32 + mt * 16 + (lane >> 2);
#pragma unroll
        for (int nt = 0; nt < 4; ++nt) {
            const int cc = n0 + wn * 32 + nt * 8 + (lane & 3) * 2;
            if (!SPLIT) {
                *(float2*)(C + (size_t)r * LDC + cc)       = make_float2(acc[mt][nt][0], acc[mt][nt][1]);
                *(float2*)(C + (size_t)(r + 8) * LDC + cc) = make_float2(acc[mt][nt][2], acc[mt][nt][3]);
            } else {
                uint32_t h, l;
                split2(acc[mt][nt][0] * premul, acc[mt][nt][1] * premul, h, l);
                *(uint32_t*)(Oh + (size_t)r * LDC + cc) = h;
                *(uint32_t*)(Ol + (size_t)r * LDC + cc) = l;
                split2(acc[mt][nt][2] * premul, acc[mt][nt][3] * premul, h, l);
                *(uint32_t*)(Oh + (size_t)(r + 8) * LDC + cc) = h;
                *(uint32_t*)(Ol + (size_t)(r + 8) * LDC + cc) = l;
            }
        }
    }
}

// ===========================================================================
// FA2-style HMMA attention. grid (LQ/128, B_*NH), 256 threads (8 warps).
// Warp w owns query rows [w*16, w*16+16). Keys padded 77 -> 80 (10 n8 tiles).
// S = (Qs)K^T via 3-term bf16 split (Q pre-scaled 0.125), fp32 softmax on
// C-fragments, P hi/lo -> A-fragments (C/A layout identity), PV 3-term vs
// smem-transposed split V. Emits bf16 hi/lo for the O-projection.
// ===========================================================================
#define AT_QH 0
#define AT_QL 16384
#define AT_KH 32768
#define AT_KL 43008
#define AT_VH 53248
#define AT_VL 64512
#define AT_SMEM 75776
#define VT_B  176   // VT row pitch bytes (88 bf16; banks 12r mod 32 distinct)

__global__ __launch_bounds__(256)
void attn_mma(const __nv_bfloat16* __restrict__ Qh, const __nv_bfloat16* __restrict__ Ql,
              const __nv_bfloat16* __restrict__ KVh, const __nv_bfloat16* __restrict__ KVl,
              __nv_bfloat16* __restrict__ Ohi, __nv_bfloat16* __restrict__ Olo)
{
    extern __shared__ char sm[];
    const uint32_t base = smem_u32(sm);
    const int tid  = threadIdx.x;
    const int w    = tid >> 5;
    const int lane = tid & 31;
    const int bh   = blockIdx.y;
    const int b    = bh >> 3;
    const int h    = bh & 7;
    const int qrow0 = b * LQ + blockIdx.x * 128;

    // zero VT region (incl. j-pad cols) and K pad rows 77..79
    for (int i = tid; i < (AT_SMEM - AT_VH) / 4; i += 256)
        ((uint32_t*)(sm + AT_VH))[i] = 0;
    if (tid < 192) {
        const int lvl = tid / 96, rr = (tid % 96) / 32, c = tid % 32;
        *(uint32_t*)(sm + (lvl ? AT_KL : AT_KH) + (77 + rr) * 128 + c * 4) = 0;
    }

    // cp.async Q tiles: 128 rows x 8 chunks x 2 levels
#pragma unroll
    for (int i = 0; i < 8; ++i) {
        const int idx = i * 256 + tid;
        const int lvl = idx >> 10;
        const int rem = idx & 1023;
        const int r = rem >> 3, c = rem & 7;
        const __nv_bfloat16* src = (lvl ? Ql : Qh) + (size_t)(qrow0 + r) * 512 + h * 64 + c * 8;
        cp_async16(base + (lvl ? AT_QL : AT_QH) + swz128((uint32_t)(r * 128 + c * 16)), src);
    }
    // cp.async K tiles: 77 rows x 8 chunks x 2 levels
#pragma unroll
    for (int i = 0; i < 5; ++i) {
        const int idx = i * 256 + tid;
        if (idx < 1232) {
            const int lvl = idx >= 616;
            const int rem = idx - lvl * 616;
            const int j = rem >> 3, c = rem & 7;
            const __nv_bfloat16* src = (lvl ? KVl : KVh) + (size_t)(b * LK + j) * 1024 + h * 64 + c * 8;
            cp_async16(base + (lvl ? AT_KL : AT_KH) + swz128((uint32_t)(j * 128 + c * 16)), src);
        }
    }
    CP_COMMIT();

    // scalar transpose V -> VT [d][j] while cp.async in flight
    for (int idx = tid; idx < 2 * LK * 64; idx += 256) {
        const int lvl = idx >= LK * 64;
        const int rem = idx - lvl * LK * 64;
        const int j = rem >> 6, d = rem & 63;
        const __nv_bfloat16 v = (lvl ? KVl : KVh)[(size_t)(b * LK + j) * 1024 + 512 + h * 64 + d];
        *(__nv_bfloat16*)(sm + (lvl ? AT_VL : AT_VH) + d * VT_B + j * 2) = v;
    }
    CP_WAIT0();
    __syncthreads();

    // ---- S = Q K^T (3-term), 10 n8 tiles ----
    float s[10][4];
#pragma unroll
    for (int nt = 0; nt < 10; ++nt)
#pragma unroll
        for (int q = 0; q < 4; ++q) s[nt][q] = 0.f;

    const uint32_t aBase = (uint32_t)((w * 16 + (lane & 15)) * 128 + (lane >> 4) * 16);
    const uint32_t bRowK = (uint32_t)(((lane & 7)) * 128 + ((lane >> 3) & 1) * 16);
#pragma unroll
    for (int kb = 0; kb < 4; ++kb) {
        const uint32_t ao = aBase + kb * 32;
        const uint32_t aso = ao ^ ((ao >> 3) & 0x70);
        uint32_t qhf[4], qlf[4];
        ldmatrix_x4(qhf, base + AT_QH + aso);
        ldmatrix_x4(qlf, base + AT_QL + aso);
#pragma unroll
        for (int nt = 0; nt < 10; ++nt) {
            const uint32_t bo = bRowK + nt * 8 * 128 + kb * 32;
            const uint32_t bso = bo ^ ((bo >> 3) & 0x70);
            uint32_t khf[2], klf[2];
            ldmatrix_x2(khf, base + AT_KH + bso);
            ldmatrix_x2(klf, base + AT_KL + bso);
            mma16816(s[nt], qhf, khf);
            mma16816(s[nt], qhf, klf);
            mma16816(s[nt], qlf, khf);
        }
    }

    // ---- mask invalid cols (j >= 77 in tile nt=9) ----
    const int t = lane & 3;
    if (t == 2) { s[9][1] = -1e30f; s[9][3] = -1e30f; }
    if (t == 3) { s[9][0] = -1e30f; s[9][1] = -1e30f; s[9][2] = -1e30f; s[9][3] = -1e30f; }

    // ---- softmax on fragments (rows g and g+8) ----
    float mlo = -1e30f, mhi = -1e30f;
#pragma unroll
    for (int nt = 0; nt < 10; ++nt) {
        mlo = fmaxf(mlo, fmaxf(s[nt][0], s[nt][1]));
        mhi = fmaxf(mhi, fmaxf(s[nt][2], s[nt][3]));
    }
#pragma unroll
    for (int o = 1; o <= 2; o <<= 1) {
        mlo = fmaxf(mlo, __shfl_xor_sync(0xffffffffu, mlo, o));
        mhi = fmaxf(mhi, __shfl_xor_sync(0xffffffffu, mhi, o));
    }
    float slo = 0.f, shi = 0.f;
#pragma unroll
    for (int nt = 0; nt < 10; ++nt) {
        s[nt][0] = __expf(s[nt][0] - mlo);
        s[nt][1] = __expf(s[nt][1] - mlo);
        s[nt][2] = __expf(s[nt][2] - mhi);
        s[nt][3] = __expf(s[nt][3] - mhi);
        slo += s[nt][0] + s[nt][1];
        shi += s[nt][2] + s[nt][3];
    }
#pragma unroll
    for (int o = 1; o <= 2; o <<= 1) {
        slo += __shfl_xor_sync(0xffffffffu, slo, o);
        shi += __shfl_xor_sync(0xffffffffu, shi, o);
    }
    const float rlo = 1.f / slo, rhi = 1.f / shi;

    // ---- O = P V (3-term), P from fragments via C->A identity ----
    float o[8][4];
#pragma unroll
    for (int dn = 0; dn < 8; ++dn)
#pragma unroll
        for (int q = 0; q < 4; ++q) o[dn][q] = 0.f;

    const uint32_t bRowV = (uint32_t)(((lane & 7)) * VT_B + ((lane >> 3) & 1) * 16);
#pragma unroll
    for (int kt = 0; kt < 5; ++kt) {
        uint32_t ph[4], pl[4];
        split2(s[2 * kt][0],     s[2 * kt][1],     ph[0], pl[0]);
        split2(s[2 * kt][2],     s[2 * kt][3],     ph[1], pl[1]);
        split2(s[2 * kt + 1][0], s[2 * kt + 1][1], ph[2], pl[2]);
        split2(s[2 * kt + 1][2], s[2 * kt + 1][3], ph[3], pl[3]);
#pragma unroll
        for (int dn = 0; dn < 8; ++dn) {
            const uint32_t bo = bRowV + dn * 8 * VT_B + kt * 32;
            uint32_t vhf[2], vlf[2];
            ldmatrix_x2(vhf, base + AT_VH + bo);
            ldmatrix_x2(vlf, base + AT_VL + bo);
            mma16816(o[dn], ph, vhf);
            mma16816(o[dn], ph, vlf);
            mma16816(o[dn], pl, vhf);
        }
    }

    // ---- epilogue: normalize + split to bf16 hi/lo ----
    const int g = lane >> 2;
    const size_t rA = (size_t)(qrow0 + w * 16 + g) * 512 + h * 64;
    const size_t rB = rA + 8 * 512;
#pragma unroll
    for (int dn = 0; dn < 8; ++dn) {
        const int col = dn * 8 + 2 * t;
        uint32_t hh, ll;
        split2(o[dn][0] * rlo, o[dn][1] * rlo, hh, ll);
        *(uint32_t*)(Ohi + rA + col) = hh;
        *(uint32_t*)(Olo + rA + col) = ll;
        split2(o[dn][2] * rhi, o[dn][3] * rhi, hh, ll);
        *(uint32_t*)(Ohi + rB + col) = hh;
        *(uint32_t*)(Olo + rB + col) = ll;
    }
}

// ===========================================================================
extern "C" void kernel_launch(void* const* d_in, const int* in_sizes, int n_in,
                              void* d_out, int out_size)
{
    (void)in_sizes; (void)n_in; (void)out_size;
    const float* x    = (const float*)d_in[0];
    const float* cond = (const float*)d_in[1];
    const float* w_q  = (const float*)d_in[2];
    const float* w_k  = (const float*)d_in[3];
    const float* w_v  = (const float*)d_in[4];
    const float* w_o  = (const float*)d_in[5];
    float* out = (float*)d_out;

    __nv_bfloat16 *xhi, *xlo, *qhi, *qlo, *ahi, *alo, *wqhi, *wqlo, *wohi, *wolo;
    __nv_bfloat16 *chi, *clo, *wkhi, *wklo, *kvhi, *kvlo;
    cudaGetSymbolAddress((void**)&xhi, g_xhi);   cudaGetSymbolAddress((void**)&xlo, g_xlo);
    cudaGetSymbolAddress((void**)&qhi, g_qhi);   cudaGetSymbolAddress((void**)&qlo, g_qlo);
    cudaGetSymbolAddress((void**)&ahi, g_ahi);   cudaGetSymbolAddress((void**)&alo, g_alo);
    cudaGetSymbolAddress((void**)&wqhi, g_wqhi); cudaGetSymbolAddress((void**)&wqlo, g_wqlo);
    cudaGetSymbolAddress((void**)&wohi, g_wohi); cudaGetSymbolAddress((void**)&wolo, g_wolo);
    cudaGetSymbolAddress((void**)&chi, g_chi);   cudaGetSymbolAddress((void**)&clo, g_clo);
    cudaGetSymbolAddress((void**)&wkhi, g_wkvhi); cudaGetSymbolAddress((void**)&wklo, g_wkvlo);
    cudaGetSymbolAddress((void**)&kvhi, g_kvhi); cudaGetSymbolAddress((void**)&kvlo, g_kvlo);

    cudaFuncSetAttribute(gemm_bf16<512, 512, false>, cudaFuncAttributeMaxDynamicSharedMemorySize, GM_SMEM);
    cudaFuncSetAttribute(gemm_bf16<512, 512, true>,  cudaFuncAttributeMaxDynamicSharedMemorySize, GM_SMEM);
    cudaFuncSetAttribute(gemm_bf16<768, 1024, true>, cudaFuncAttributeMaxDynamicSharedMemorySize, GM_SMEM);
    cudaFuncSetAttribute(attn_mma, cudaFuncAttributeMaxDynamicSharedMemorySize, AT_SMEM);

    // Pre-split to bf16 hi/lo
    const int XN4 = B_ * LQ * DMODEL / 4;
    const int WN4 = DMODEL * INNER / 4;
    const int CN4 = MKV * DCOND / 4;
    const int WKN4 = INNER * DCOND / 4;
    cvt_split<<<(XN4 + 255) / 256, 256>>>((const float4*)x, (uint2*)xhi, (uint2*)xlo, XN4);
    cvt_split<<<(WN4 + 255) / 256, 256>>>((const float4*)w_q, (uint2*)wqhi, (uint2*)wqlo, WN4);
    cvt_split<<<(WN4 + 255) / 256, 256>>>((const float4*)w_o, (uint2*)wohi, (uint2*)wolo, WN4);
    cvt_split<<<(CN4 + 255) / 256, 256>>>((const float4*)cond, (uint2*)chi, (uint2*)clo, CN4);
    cvt_split<<<(WKN4 + 255) / 256, 256>>>((const float4*)w_k, (uint2*)wkhi, (uint2*)wklo, WKN4);
    cvt_split<<<(WKN4 + 255) / 256, 256>>>((const float4*)w_v,
        (uint2*)(wkhi + (size_t)INNER * DCOND), (uint2*)(wklo + (size_t)INNER * DCOND), WKN4);

    // K+V projection -> split bf16 [MKVP,1024]
    gemm_bf16<768, 1024, true><<<dim3(MKVP / 128, 8), 512, GM_SMEM>>>(
        chi, clo, wkhi, wklo, nullptr, kvhi, kvlo, 1.f);

    // Q projection -> split bf16, pre-scaled by 1/sqrt(64)
    gemm_bf16<512, 512, true><<<dim3(512, 4), 512, GM_SMEM>>>(
        xhi, xlo, wqhi, wqlo, nullptr, qhi, qlo, 0.125f);

    // Tensor-core attention -> split bf16
    attn_mma<<<dim3(LQ / 128, B_ * NH), 256, AT_SMEM>>>(qhi, qlo, kvhi, kvlo, ahi, alo);

    // Output projection -> fp32
    gemm_bf16<512, 512, false><<<dim3(512, 4), 512, GM_SMEM>>>(
        ahi, alo, wohi, wolo, out, nullptr, nullptr, 1.f);
}

// round 10
// speedup vs baseline: 3.9086x; 1.2741x over previous
#include <cuda_runtime.h>
#include <cuda_bf16.h>
#include <cuda_fp16.h>
#include <cstdint>
#include <math.h>

#define B_     16
#define LQ     4096
#define LK     77
#define DMODEL 512
#define DCOND  768
#define NH     8
#define HD     64
#define INNER  512   // NH*HD
#define MKV    1232  // B_*LK
#define MKVP   1280  // padded to 128

// Scratch (allocation-free rule: __device__ globals; zero-initialized)
__device__ __half g_xh[(size_t)B_ * LQ * DMODEL];          // x fp16
__device__ __half g_ch[MKVP * DCOND];                      // cond fp16 (pad rows 0)
__device__ __half g_ah[(size_t)B_ * LQ * INNER];           // attention out fp16
__device__ __half g_wqh[DMODEL * INNER];
__device__ __half g_wql[DMODEL * INNER];
__device__ __half g_woh[DMODEL * INNER];
__device__ __half g_wol[DMODEL * INNER];
__device__ __half g_wkvh[2 * INNER * DCOND];               // [w_k ; w_v]
__device__ __half g_wkvl[2 * INNER * DCOND];
__device__ __nv_bfloat16 g_qhi[(size_t)B_ * LQ * INNER];   // Q*0.125 bf16 split
__device__ __nv_bfloat16 g_qlo[(size_t)B_ * LQ * INNER];
__device__ __nv_bfloat16 g_kvhi[(size_t)MKVP * 1024];      // K cols 0..511, V 512..1023
__device__ __nv_bfloat16 g_kvlo[(size_t)MKVP * 1024];

// ===========================================================================
// Helpers (base PTX only)
// ===========================================================================
__device__ __forceinline__ uint32_t smem_u32(const void* p) {
    uint32_t a;
    asm("{ .reg .u64 t; cvta.to.shared.u64 t, %1; cvt.u32.u64 %0, t; }" : "=r"(a) : "l"(p));
    return a;
}
__device__ __forceinline__ uint32_t swz128(uint32_t off) { return off ^ ((off >> 3) & 0x70); }

__device__ __forceinline__ void ldmatrix_x4(uint32_t* r, uint32_t addr) {
    asm volatile("ldmatrix.sync.aligned.m8n8.x4.shared.b16 {%0,%1,%2,%3}, [%4];"
        : "=r"(r[0]), "=r"(r[1]), "=r"(r[2]), "=r"(r[3]) : "r"(addr));
}
__device__ __forceinline__ void ldmatrix_x2(uint32_t* r, uint32_t addr) {
    asm volatile("ldmatrix.sync.aligned.m8n8.x2.shared.b16 {%0,%1}, [%2];"
        : "=r"(r[0]), "=r"(r[1]) : "r"(addr));
}
// bf16 MMA (attention)
__device__ __forceinline__ void mma16816(float* d, const uint32_t* a, const uint32_t* b) {
    asm volatile("mma.sync.aligned.m16n8k16.row.col.f32.bf16.bf16.f32 "
        "{%0,%1,%2,%3}, {%4,%5,%6,%7}, {%8,%9}, {%0,%1,%2,%3};"
        : "+f"(d[0]), "+f"(d[1]), "+f"(d[2]), "+f"(d[3])
        : "r"(a[0]), "r"(a[1]), "r"(a[2]), "r"(a[3]), "r"(b[0]), "r"(b[1]));
}
// fp16 MMA (projections)
__device__ __forceinline__ void mma16816h(float* d, const uint32_t* a, const uint32_t* b) {
    asm volatile("mma.sync.aligned.m16n8k16.row.col.f32.f16.f16.f32 "
        "{%0,%1,%2,%3}, {%4,%5,%6,%7}, {%8,%9}, {%0,%1,%2,%3};"
        : "+f"(d[0]), "+f"(d[1]), "+f"(d[2]), "+f"(d[3])
        : "r"(a[0]), "r"(a[1]), "r"(a[2]), "r"(a[3]), "r"(b[0]), "r"(b[1]));
}
__device__ __forceinline__ void cp_async16(uint32_t dst, const void* src) {
    asm volatile("cp.async.cg.shared.global [%0], [%1], 16;" :: "r"(dst), "l"(src));
}
#define CP_COMMIT() asm volatile("cp.async.commit_group;" ::: "memory")
#define CP_WAIT3()  asm volatile("cp.async.wait_group 3;" ::: "memory")
#define CP_WAIT0()  asm volatile("cp.async.wait_group 0;" ::: "memory")

// split two floats into packed bf16x2 hi + residual lo
__device__ __forceinline__ void split2(float x, float y, uint32_t& hi, uint32_t& lo) {
    __nv_bfloat16 hx = __float2bfloat16_rn(x), hy = __float2bfloat16_rn(y);
    __nv_bfloat16 lx = __float2bfloat16_rn(x - __bfloat162float(hx));
    __nv_bfloat16 ly = __float2bfloat16_rn(y - __bfloat162float(hy));
    hi = (uint32_t)__bfloat16_as_ushort(hx) | ((uint32_t)__bfloat16_as_ushort(hy) << 16);
    lo = (uint32_t)__bfloat16_as_ushort(lx) | ((uint32_t)__bfloat16_as_ushort(ly) << 16);
}
__device__ __forceinline__ uint32_t pack_h2(float x, float y) {
    __half2 h = __floats2half2_rn(x, y);
    return *(const uint32_t*)&h;
}

// fp32 -> single fp16
__global__ void cvt_h(const float4* __restrict__ in, uint2* __restrict__ out, int n4)
{
    const int i = blockIdx.x * blockDim.x + threadIdx.x;
    if (i >= n4) return;
    const float4 v = in[i];
    out[i] = make_uint2(pack_h2(v.x, v.y), pack_h2(v.z, v.w));
}
// fp32 -> fp16 hi + residual lo
__global__ void cvt_h2(const float4* __restrict__ in, uint2* __restrict__ hi,
                       uint2* __restrict__ lo, int n4)
{
    const int i = blockIdx.x * blockDim.x + threadIdx.x;
    if (i >= n4) return;
    const float4 v = in[i];
    const __half hx = __float2half_rn(v.x), hy = __float2half_rn(v.y);
    const __half hz = __float2half_rn(v.z), hw = __float2half_rn(v.w);
    hi[i] = make_uint2(
        (uint32_t)__half_as_ushort(hx) | ((uint32_t)__half_as_ushort(hy) << 16),
        (uint32_t)__half_as_ushort(hz) | ((uint32_t)__half_as_ushort(hw) << 16));
    lo[i] = make_uint2(
        pack_h2(v.x - __half2float(hx), v.y - __half2float(hy)),
        pack_h2(v.z - __half2float(hz), v.w - __half2float(hw)));
}

// ===========================================================================
// fp16 HMMA GEMM: C = A (Bh+Bl)^T, A single fp16 (error from A rounding only),
// B = weights split 2-term. 2 MMAs per k16 (vs 3 for bf16-split).
// 128x128 tile, K-chunk 64, 4-stage cp.async (48KB/stage), 512 thr, 32x32 warp.
// SPLIT=true: bf16 hi/lo premul outputs (feeds attention); else fp32 C.
// ===========================================================================
#define GM_SMEM (4 * 49152)

template <int KDIM, int LDC, bool SPLIT>
__global__ void __launch_bounds__(512, 1)
gemm_f16(const __half* __restrict__ A, const __half* __restrict__ Bh,
         const __half* __restrict__ Bl, float* __restrict__ C,
         __nv_bfloat16* __restrict__ Oh, __nv_bfloat16* __restrict__ Ol, float premul)
{
    constexpr int NCHUNK = KDIM / 64;
    extern __shared__ char sm[];
    const uint32_t base = smem_u32(sm);
    const int tid  = threadIdx.x;
    const int wid  = tid >> 5;
    const int lane = tid & 31;
    const int wm   = wid & 3;
    const int wn   = wid >> 2;

    const int m0 = blockIdx.x * 128;
    const int n0 = blockIdx.y * 128;
    const __half* A0  = A  + (size_t)m0 * KDIM;
    const __half* Bh0 = Bh + (size_t)n0 * KDIM;
    const __half* Bl0 = Bl + (size_t)n0 * KDIM;

    float acc[2][4][4];
#pragma unroll
    for (int mt = 0; mt < 2; ++mt)
#pragma unroll
        for (int nt = 0; nt < 4; ++nt)
#pragma unroll
            for (int q = 0; q < 4; ++q) acc[mt][nt][q] = 0.f;

    uint32_t aRow0[2], bRow0[4];
#pragma unroll
    for (int mt = 0; mt < 2; ++mt)
        aRow0[mt] = (uint32_t)((wm * 32 + mt * 16 + (lane & 15)) * 128 + (lane >> 4) * 16);
#pragma unroll
    for (int nt = 0; nt < 4; ++nt)
        bRow0[nt] = (uint32_t)((wn * 32 + nt * 8 + (lane & 7)) * 128 + ((lane >> 3) & 1) * 16);

    auto issue_chunk = [&](int c, int buf) {
        const int kc = c * 64;
        const uint32_t tb = base + buf * 49152;
#pragma unroll
        for (int i = 0; i < 2; ++i) {
            const int idx = i * 512 + tid;      // 0..1023
            const int row = idx >> 3;
            const int c16 = idx & 7;
            const uint32_t so = swz128((uint32_t)(row * 128 + c16 * 16));
            const size_t go = (size_t)row * KDIM + kc + c16 * 8;
            cp_async16(tb + so,         A0  + go);
            cp_async16(tb + 16384 + so, Bh0 + go);
            cp_async16(tb + 32768 + so, Bl0 + go);
        }
    };

    issue_chunk(0, 0); CP_COMMIT();
    issue_chunk(1, 1); CP_COMMIT();
    issue_chunk(2, 2); CP_COMMIT();
    issue_chunk(3, 3); CP_COMMIT();

    for (int c = 0; c < NCHUNK; ++c) {
        const int buf = c & 3;
        CP_WAIT3();
        __syncthreads();

        const uint32_t bufA = base + buf * 49152;
        const uint32_t bufB = bufA + 16384;
#pragma unroll
        for (int kb = 0; kb < 4; ++kb) {
            const uint32_t kbyte = kb * 32;
            uint32_t Af[2][4], Bhf[4][2], Blf[4][2];
#pragma unroll
            for (int mt = 0; mt < 2; ++mt) {
                const uint32_t off = aRow0[mt] + kbyte;
                ldmatrix_x4(Af[mt], bufA + (off ^ ((off >> 3) & 0x70)));
            }
#pragma unroll
            for (int nt = 0; nt < 4; ++nt) {
                const uint32_t off = bRow0[nt] + kbyte;
                const uint32_t so  = off ^ ((off >> 3) & 0x70);
                ldmatrix_x2(Bhf[nt], bufB + so);
                ldmatrix_x2(Blf[nt], bufB + 16384 + so);
            }
#pragma unroll
            for (int mt = 0; mt < 2; ++mt)
#pragma unroll
                for (int nt = 0; nt < 4; ++nt)
                    mma16816h(acc[mt][nt], Af[mt], Bhf[nt]);
#pragma unroll
            for (int mt = 0; mt < 2; ++mt)
#pragma unroll
                for (int nt = 0; nt < 4; ++nt)
                    mma16816h(acc[mt][nt], Af[mt], Blf[nt]);
        }
        __syncthreads();
        if (c + 4 < NCHUNK) issue_chunk(c + 4, buf);
        CP_COMMIT();
    }

#pragma unroll
    for (int mt = 0; mt < 2; ++mt) {
        const int r = m0 + wm * 32 + mt * 16 + (lane >> 2);
#pragma unroll
        for (int nt = 0; nt < 4; ++nt) {
            const int cc = n0 + wn * 32 + nt * 8 + (lane & 3) * 2;
            if (!SPLIT) {
                *(float2*)(C + (size_t)r * LDC + cc)       = make_float2(acc[mt][nt][0], acc[mt][nt][1]);
                *(float2*)(C + (size_t)(r + 8) * LDC + cc) = make_float2(acc[mt][nt][2], acc[mt][nt][3]);
            } else {
                uint32_t h, l;
                split2(acc[mt][nt][0] * premul, acc[mt][nt][1] * premul, h, l);
                *(uint32_t*)(Oh + (size_t)r * LDC + cc) = h;
                *(uint32_t*)(Ol + (size_t)r * LDC + cc) = l;
                split2(acc[mt][nt][2] * premul, acc[mt][nt][3] * premul, h, l);
                *(uint32_t*)(Oh + (size_t)(r + 8) * LDC + cc) = h;
                *(uint32_t*)(Ol + (size_t)(r + 8) * LDC + cc) = l;
            }
        }
    }
}

// ===========================================================================
// FA2-style HMMA attention (bf16 3-term, unchanged math). Emits fp16 single
// for the O-projection. grid (LQ/128, B_*NH), 256 threads.
// ===========================================================================
#define AT_QH 0
#define AT_QL 16384
#define AT_KH 32768
#define AT_KL 43008
#define AT_VH 53248
#define AT_VL 64512
#define AT_SMEM 75776
#define VT_B  176

__global__ __launch_bounds__(256)
void attn_mma(const __nv_bfloat16* __restrict__ Qh, const __nv_bfloat16* __restrict__ Ql,
              const __nv_bfloat16* __restrict__ KVh, const __nv_bfloat16* __restrict__ KVl,
              __half* __restrict__ Oa)
{
    extern __shared__ char sm[];
    const uint32_t base = smem_u32(sm);
    const int tid  = threadIdx.x;
    const int w    = tid >> 5;
    const int lane = tid & 31;
    const int bh   = blockIdx.y;
    const int b    = bh >> 3;
    const int h    = bh & 7;
    const int qrow0 = b * LQ + blockIdx.x * 128;

    for (int i = tid; i < (AT_SMEM - AT_VH) / 4; i += 256)
        ((uint32_t*)(sm + AT_VH))[i] = 0;
    if (tid < 192) {
        const int lvl = tid / 96, rr = (tid % 96) / 32, c = tid % 32;
        *(uint32_t*)(sm + (lvl ? AT_KL : AT_KH) + (77 + rr) * 128 + c * 4) = 0;
    }

#pragma unroll
    for (int i = 0; i < 8; ++i) {
        const int idx = i * 256 + tid;
        const int lvl = idx >> 10;
        const int rem = idx & 1023;
        const int r = rem >> 3, c = rem & 7;
        const __nv_bfloat16* src = (lvl ? Ql : Qh) + (size_t)(qrow0 + r) * 512 + h * 64 + c * 8;
        cp_async16(base + (lvl ? AT_QL : AT_QH) + swz128((uint32_t)(r * 128 + c * 16)), src);
    }
#pragma unroll
    for (int i = 0; i < 5; ++i) {
        const int idx = i * 256 + tid;
        if (idx < 1232) {
            const int lvl = idx >= 616;
            const int rem = idx - lvl * 616;
            const int j = rem >> 3, c = rem & 7;
            const __nv_bfloat16* src = (lvl ? KVl : KVh) + (size_t)(b * LK + j) * 1024 + h * 64 + c * 8;
            cp_async16(base + (lvl ? AT_KL : AT_KH) + swz128((uint32_t)(j * 128 + c * 16)), src);
        }
    }
    CP_COMMIT();

    for (int idx = tid; idx < 2 * LK * 64; idx += 256) {
        const int lvl = idx >= LK * 64;
        const int rem = idx - lvl * LK * 64;
        const int j = rem >> 6, d = rem & 63;
        const __nv_bfloat16 v = (lvl ? KVl : KVh)[(size_t)(b * LK + j) * 1024 + 512 + h * 64 + d];
        *(__nv_bfloat16*)(sm + (lvl ? AT_VL : AT_VH) + d * VT_B + j * 2) = v;
    }
    CP_WAIT0();
    __syncthreads();

    float s[10][4];
#pragma unroll
    for (int nt = 0; nt < 10; ++nt)
#pragma unroll
        for (int q = 0; q < 4; ++q) s[nt][q] = 0.f;

    const uint32_t aBase = (uint32_t)((w * 16 + (lane & 15)) * 128 + (lane >> 4) * 16);
    const uint32_t bRowK = (uint32_t)(((lane & 7)) * 128 + ((lane >> 3) & 1) * 16);
#pragma unroll
    for (int kb = 0; kb < 4; ++kb) {
        const uint32_t ao = aBase + kb * 32;
        const uint32_t aso = ao ^ ((ao >> 3) & 0x70);
        uint32_t qhf[4], qlf[4];
        ldmatrix_x4(qhf, base + AT_QH + aso);
        ldmatrix_x4(qlf, base + AT_QL + aso);
#pragma unroll
        for (int nt = 0; nt < 10; ++nt) {
            const uint32_t bo = bRowK + nt * 8 * 128 + kb * 32;
            const uint32_t bso = bo ^ ((bo >> 3) & 0x70);
            uint32_t khf[2], klf[2];
            ldmatrix_x2(khf, base + AT_KH + bso);
            ldmatrix_x2(klf, base + AT_KL + bso);
            mma16816(s[nt], qhf, khf);
            mma16816(s[nt], qhf, klf);
            mma16816(s[nt], qlf, khf);
        }
    }

    const int t = lane & 3;
    if (t == 2) { s[9][1] = -1e30f; s[9][3] = -1e30f; }
    if (t == 3) { s[9][0] = -1e30f; s[9][1] = -1e30f; s[9][2] = -1e30f; s[9][3] = -1e30f; }

    float mlo = -1e30f, mhi = -1e30f;
#pragma unroll
    for (int nt = 0; nt < 10; ++nt) {
        mlo = fmaxf(mlo, fmaxf(s[nt][0], s[nt][1]));
        mhi = fmaxf(mhi, fmaxf(s[nt][2], s[nt][3]));
    }
#pragma unroll
    for (int o = 1; o <= 2; o <<= 1) {
        mlo = fmaxf(mlo, __shfl_xor_sync(0xffffffffu, mlo, o));
        mhi = fmaxf(mhi, __shfl_xor_sync(0xffffffffu, mhi, o));
    }
    float slo = 0.f, shi = 0.f;
#pragma unroll
    for (int nt = 0; nt < 10; ++nt) {
        s[nt][0] = __expf(s[nt][0] - mlo);
        s[nt][1] = __expf(s[nt][1] - mlo);
        s[nt][2] = __expf(s[nt][2] - mhi);
        s[nt][3] = __expf(s[nt][3] - mhi);
        slo += s[nt][0] + s[nt][1];
        shi += s[nt][2] + s[nt][3];
    }
#pragma unroll
    for (int o = 1; o <= 2; o <<= 1) {
        slo += __shfl_xor_sync(0xffffffffu, slo, o);
        shi += __shfl_xor_sync(0xffffffffu, shi, o);
    }
    const float rlo = 1.f / slo, rhi = 1.f / shi;

    float o[8][4];
#pragma unroll
    for (int dn = 0; dn < 8; ++dn)
#pragma unroll
        for (int q = 0; q < 4; ++q) o[dn][q] = 0.f;

    const uint32_t bRowV = (uint32_t)(((lane & 7)) * VT_B + ((lane >> 3) & 1) * 16);
#pragma unroll
    for (int kt = 0; kt < 5; ++kt) {
        uint32_t ph[4], pl[4];
        split2(s[2 * kt][0],     s[2 * kt][1],     ph[0], pl[0]);
        split2(s[2 * kt][2],     s[2 * kt][3],     ph[1], pl[1]);
        split2(s[2 * kt + 1][0], s[2 * kt + 1][1], ph[2], pl[2]);
        split2(s[2 * kt + 1][2], s[2 * kt + 1][3], ph[3], pl[3]);
#pragma unroll
        for (int dn = 0; dn < 8; ++dn) {
            const uint32_t bo = bRowV + dn * 8 * VT_B + kt * 32;
            uint32_t vhf[2], vlf[2];
            ldmatrix_x2(vhf, base + AT_VH + bo);
            ldmatrix_x2(vlf, base + AT_VL + bo);
            mma16816(o[dn], ph, vhf);
            mma16816(o[dn], ph, vlf);
            mma16816(o[dn], pl, vhf);
        }
    }

    const int g = lane >> 2;
    const size_t rA = (size_t)(qrow0 + w * 16 + g) * 512 + h * 64;
    const size_t rB = rA + 8 * 512;
#pragma unroll
    for (int dn = 0; dn < 8; ++dn) {
        const int col = dn * 8 + 2 * t;
        *(uint32_t*)(Oa + rA + col) = pack_h2(o[dn][0] * rlo, o[dn][1] * rlo);
        *(uint32_t*)(Oa + rB + col) = pack_h2(o[dn][2] * rhi, o[dn][3] * rhi);
    }
}

// ===========================================================================
extern "C" void kernel_launch(void* const* d_in, const int* in_sizes, int n_in,
                              void* d_out, int out_size)
{
    (void)in_sizes; (void)n_in; (void)out_size;
    const float* x    = (const float*)d_in[0];
    const float* cond = (const float*)d_in[1];
    const float* w_q  = (const float*)d_in[2];
    const float* w_k  = (const float*)d_in[3];
    const float* w_v  = (const float*)d_in[4];
    const float* w_o  = (const float*)d_in[5];
    float* out = (float*)d_out;

    __half *xh, *ch, *ah, *wqh, *wql, *woh, *wol, *wkvh, *wkvl;
    __nv_bfloat16 *qhi, *qlo, *kvhi, *kvlo;
    cudaGetSymbolAddress((void**)&xh, g_xh);
    cudaGetSymbolAddress((void**)&ch, g_ch);
    cudaGetSymbolAddress((void**)&ah, g_ah);
    cudaGetSymbolAddress((void**)&wqh, g_wqh);   cudaGetSymbolAddress((void**)&wql, g_wql);
    cudaGetSymbolAddress((void**)&woh, g_woh);   cudaGetSymbolAddress((void**)&wol, g_wol);
    cudaGetSymbolAddress((void**)&wkvh, g_wkvh); cudaGetSymbolAddress((void**)&wkvl, g_wkvl);
    cudaGetSymbolAddress((void**)&qhi, g_qhi);   cudaGetSymbolAddress((void**)&qlo, g_qlo);
    cudaGetSymbolAddress((void**)&kvhi, g_kvhi); cudaGetSymbolAddress((void**)&kvlo, g_kvlo);

    cudaFuncSetAttribute(gemm_f16<512, 512, false>, cudaFuncAttributeMaxDynamicSharedMemorySize, GM_SMEM);
    cudaFuncSetAttribute(gemm_f16<512, 512, true>,  cudaFuncAttributeMaxDynamicSharedMemorySize, GM_SMEM);
    cudaFuncSetAttribute(gemm_f16<768, 1024, true>, cudaFuncAttributeMaxDynamicSharedMemorySize, GM_SMEM);
    cudaFuncSetAttribute(attn_mma, cudaFuncAttributeMaxDynamicSharedMemorySize, AT_SMEM);

    const int XN4 = B_ * LQ * DMODEL / 4;
    const int WN4 = DMODEL * INNER / 4;
    const int CN4 = MKV * DCOND / 4;
    const int WKN4 = INNER * DCOND / 4;
    // activations: single fp16
    cvt_h<<<(XN4 + 255) / 256, 256>>>((const float4*)x, (uint2*)xh, XN4);
    cvt_h<<<(CN4 + 255) / 256, 256>>>((const float4*)cond, (uint2*)ch, CN4);
    // weights: fp16 hi/lo 2-term
    cvt_h2<<<(WN4 + 255) / 256, 256>>>((const float4*)w_q, (uint2*)wqh, (uint2*)wql, WN4);
    cvt_h2<<<(WN4 + 255) / 256, 256>>>((const float4*)w_o, (uint2*)woh, (uint2*)wol, WN4);
    cvt_h2<<<(WKN4 + 255) / 256, 256>>>((const float4*)w_k, (uint2*)wkvh, (uint2*)wkvl, WKN4);
    cvt_h2<<<(WKN4 + 255) / 256, 256>>>((const float4*)w_v,
        (uint2*)(wkvh + (size_t)INNER * DCOND), (uint2*)(wkvl + (size_t)INNER * DCOND), WKN4);

    // K+V projection -> bf16 hi/lo [MKVP,1024]
    gemm_f16<768, 1024, true><<<dim3(MKVP / 128, 8), 512, GM_SMEM>>>(
        ch, wkvh, wkvl, nullptr, kvhi, kvlo, 1.f);

    // Q projection -> bf16 hi/lo, pre-scaled 1/sqrt(64)
    gemm_f16<512, 512, true><<<dim3(512, 4), 512, GM_SMEM>>>(
        xh, wqh, wql, nullptr, qhi, qlo, 0.125f);

    // Tensor-core attention -> fp16 single
    attn_mma<<<dim3(LQ / 128, B_ * NH), 256, AT_SMEM>>>(qhi, qlo, kvhi, kvlo, ah);

    // Output projection -> fp32
    gemm_f16<512, 512, false><<<dim3(512, 4), 512, GM_SMEM>>>(
        ah, woh, wol, out, nullptr, nullptr, 1.f);
}

// round 11
// speedup vs baseline: 4.7871x; 1.2248x over previous
#include <cuda_runtime.h>
#include <cuda_bf16.h>
#include <cuda_fp16.h>
#include <cstdint>
#include <math.h>

#define B_     16
#define LQ     4096
#define LK     77
#define DMODEL 512
#define DCOND  768
#define NH     8
#define HD     64
#define INNER  512   // NH*HD
#define MKV    1232  // B_*LK
#define MKVP   1280  // padded to 128

// Scratch (allocation-free rule: __device__ globals; zero-initialized)
__device__ __half g_xh[(size_t)B_ * LQ * DMODEL];          // x fp16
__device__ __half g_ch[MKVP * DCOND];                      // cond fp16 (pad rows 0)
__device__ __half g_ah[(size_t)B_ * LQ * INNER];           // attention out fp16
__device__ __half g_wqh[DMODEL * INNER];                   // w_q single fp16
__device__ __half g_woh[DMODEL * INNER];                   // w_o single fp16
__device__ __half g_wkvh[2 * INNER * DCOND];               // [w_k ; w_v] 2-term
__device__ __half g_wkvl[2 * INNER * DCOND];
__device__ __nv_bfloat16 g_qhi[(size_t)B_ * LQ * INNER];   // Q*0.125 bf16 split
__device__ __nv_bfloat16 g_qlo[(size_t)B_ * LQ * INNER];
__device__ __nv_bfloat16 g_kvhi[(size_t)MKVP * 1024];      // K cols 0..511, V 512..1023
__device__ __nv_bfloat16 g_kvlo[(size_t)MKVP * 1024];

// ===========================================================================
// Helpers (base PTX only)
// ===========================================================================
__device__ __forceinline__ uint32_t smem_u32(const void* p) {
    uint32_t a;
    asm("{ .reg .u64 t; cvta.to.shared.u64 t, %1; cvt.u32.u64 %0, t; }" : "=r"(a) : "l"(p));
    return a;
}
__device__ __forceinline__ uint32_t swz128(uint32_t off) { return off ^ ((off >> 3) & 0x70); }

__device__ __forceinline__ void ldmatrix_x4(uint32_t* r, uint32_t addr) {
    asm volatile("ldmatrix.sync.aligned.m8n8.x4.shared.b16 {%0,%1,%2,%3}, [%4];"
        : "=r"(r[0]), "=r"(r[1]), "=r"(r[2]), "=r"(r[3]) : "r"(addr));
}
__device__ __forceinline__ void ldmatrix_x2(uint32_t* r, uint32_t addr) {
    asm volatile("ldmatrix.sync.aligned.m8n8.x2.shared.b16 {%0,%1}, [%2];"
        : "=r"(r[0]), "=r"(r[1]) : "r"(addr));
}
// bf16 MMA (attention)
__device__ __forceinline__ void mma16816(float* d, const uint32_t* a, const uint32_t* b) {
    asm volatile("mma.sync.aligned.m16n8k16.row.col.f32.bf16.bf16.f32 "
        "{%0,%1,%2,%3}, {%4,%5,%6,%7}, {%8,%9}, {%0,%1,%2,%3};"
        : "+f"(d[0]), "+f"(d[1]), "+f"(d[2]), "+f"(d[3])
        : "r"(a[0]), "r"(a[1]), "r"(a[2]), "r"(a[3]), "r"(b[0]), "r"(b[1]));
}
// fp16 MMA (projections)
__device__ __forceinline__ void mma16816h(float* d, const uint32_t* a, const uint32_t* b) {
    asm volatile("mma.sync.aligned.m16n8k16.row.col.f32.f16.f16.f32 "
        "{%0,%1,%2,%3}, {%4,%5,%6,%7}, {%8,%9}, {%0,%1,%2,%3};"
        : "+f"(d[0]), "+f"(d[1]), "+f"(d[2]), "+f"(d[3])
        : "r"(a[0]), "r"(a[1]), "r"(a[2]), "r"(a[3]), "r"(b[0]), "r"(b[1]));
}
__device__ __forceinline__ void cp_async16(uint32_t dst, const void* src) {
    asm volatile("cp.async.cg.shared.global [%0], [%1], 16;" :: "r"(dst), "l"(src));
}
#define CP_COMMIT() asm volatile("cp.async.commit_group;" ::: "memory")
#define CP_WAIT3()  asm volatile("cp.async.wait_group 3;" ::: "memory")
#define CP_WAIT0()  asm volatile("cp.async.wait_group 0;" ::: "memory")

// split two floats into packed bf16x2 hi + residual lo
__device__ __forceinline__ void split2(float x, float y, uint32_t& hi, uint32_t& lo) {
    __nv_bfloat16 hx = __float2bfloat16_rn(x), hy = __float2bfloat16_rn(y);
    __nv_bfloat16 lx = __float2bfloat16_rn(x - __bfloat162float(hx));
    __nv_bfloat16 ly = __float2bfloat16_rn(y - __bfloat162float(hy));
    hi = (uint32_t)__bfloat16_as_ushort(hx) | ((uint32_t)__bfloat16_as_ushort(hy) << 16);
    lo = (uint32_t)__bfloat16_as_ushort(lx) | ((uint32_t)__bfloat16_as_ushort(ly) << 16);
}
__device__ __forceinline__ uint32_t pack_h2(float x, float y) {
    __half2 h = __floats2half2_rn(x, y);
    return *(const uint32_t*)&h;
}

// fp32 -> single fp16
__global__ void cvt_h(const float4* __restrict__ in, uint2* __restrict__ out, int n4)
{
    const int i = blockIdx.x * blockDim.x + threadIdx.x;
    if (i >= n4) return;
    const float4 v = in[i];
    out[i] = make_uint2(pack_h2(v.x, v.y), pack_h2(v.z, v.w));
}
// fp32 -> fp16 hi + residual lo
__global__ void cvt_h2(const float4* __restrict__ in, uint2* __restrict__ hi,
                       uint2* __restrict__ lo, int n4)
{
    const int i = blockIdx.x * blockDim.x + threadIdx.x;
    if (i >= n4) return;
    const float4 v = in[i];
    const __half hx = __float2half_rn(v.x), hy = __float2half_rn(v.y);
    const __half hz = __float2half_rn(v.z), hw = __float2half_rn(v.w);
    hi[i] = make_uint2(
        (uint32_t)__half_as_ushort(hx) | ((uint32_t)__half_as_ushort(hy) << 16),
        (uint32_t)__half_as_ushort(hz) | ((uint32_t)__half_as_ushort(hw) << 16));
    lo[i] = make_uint2(
        pack_h2(v.x - __half2float(hx), v.y - __half2float(hy)),
        pack_h2(v.z - __half2float(hz), v.w - __half2float(hw)));
}

// ===========================================================================
// fp16 HMMA GEMM: C = A B^T (TWOB=false, 1 MMA/k16) or A (Bh+Bl)^T (TWOB=true).
// A single fp16. 128x128 tile, K-chunk 64, 4-stage cp.async, 512 thr, 32x32 warp.
// SPLIT=true: bf16 hi/lo premul outputs; else fp32 C.
// Stage size: 32KB (single B) or 48KB (2-term B).
// ===========================================================================
#define GM_SMEM_1 (4 * 32768)
#define GM_SMEM_2 (4 * 49152)

template <int KDIM, int LDC, bool SPLIT, bool TWOB>
__global__ void __launch_bounds__(512, 1)
gemm_f16(const __half* __restrict__ A, const __half* __restrict__ Bh,
         const __half* __restrict__ Bl, float* __restrict__ C,
         __nv_bfloat16* __restrict__ Oh, __nv_bfloat16* __restrict__ Ol, float premul)
{
    constexpr int NCHUNK = KDIM / 64;
    constexpr int STAGE  = TWOB ? 49152 : 32768;
    extern __shared__ char sm[];
    const uint32_t base = smem_u32(sm);
    const int tid  = threadIdx.x;
    const int wid  = tid >> 5;
    const int lane = tid & 31;
    const int wm   = wid & 3;
    const int wn   = wid >> 2;

    const int m0 = blockIdx.x * 128;
    const int n0 = blockIdx.y * 128;
    const __half* A0  = A  + (size_t)m0 * KDIM;
    const __half* Bh0 = Bh + (size_t)n0 * KDIM;
    const __half* Bl0 = TWOB ? (Bl + (size_t)n0 * KDIM) : nullptr;

    float acc[2][4][4];
#pragma unroll
    for (int mt = 0; mt < 2; ++mt)
#pragma unroll
        for (int nt = 0; nt < 4; ++nt)
#pragma unroll
            for (int q = 0; q < 4; ++q) acc[mt][nt][q] = 0.f;

    uint32_t aRow0[2], bRow0[4];
#pragma unroll
    for (int mt = 0; mt < 2; ++mt)
        aRow0[mt] = (uint32_t)((wm * 32 + mt * 16 + (lane & 15)) * 128 + (lane >> 4) * 16);
#pragma unroll
    for (int nt = 0; nt < 4; ++nt)
        bRow0[nt] = (uint32_t)((wn * 32 + nt * 8 + (lane & 7)) * 128 + ((lane >> 3) & 1) * 16);

    auto issue_chunk = [&](int c, int buf) {
        const int kc = c * 64;
        const uint32_t tb = base + buf * STAGE;
#pragma unroll
        for (int i = 0; i < 2; ++i) {
            const int idx = i * 512 + tid;      // 0..1023
            const int row = idx >> 3;
            const int c16 = idx & 7;
            const uint32_t so = swz128((uint32_t)(row * 128 + c16 * 16));
            const size_t go = (size_t)row * KDIM + kc + c16 * 8;
            cp_async16(tb + so,         A0  + go);
            cp_async16(tb + 16384 + so, Bh0 + go);
            if (TWOB) cp_async16(tb + 32768 + so, Bl0 + go);
        }
    };

    issue_chunk(0, 0); CP_COMMIT();
    issue_chunk(1, 1); CP_COMMIT();
    issue_chunk(2, 2); CP_COMMIT();
    issue_chunk(3, 3); CP_COMMIT();

    for (int c = 0; c < NCHUNK; ++c) {
        const int buf = c & 3;
        CP_WAIT3();
        __syncthreads();

        const uint32_t bufA = base + buf * STAGE;
        const uint32_t bufB = bufA + 16384;
#pragma unroll
        for (int kb = 0; kb < 4; ++kb) {
            const uint32_t kbyte = kb * 32;
            uint32_t Af[2][4], Bhf[4][2], Blf[4][2];
#pragma unroll
            for (int mt = 0; mt < 2; ++mt) {
                const uint32_t off = aRow0[mt] + kbyte;
                ldmatrix_x4(Af[mt], bufA + (off ^ ((off >> 3) & 0x70)));
            }
#pragma unroll
            for (int nt = 0; nt < 4; ++nt) {
                const uint32_t off = bRow0[nt] + kbyte;
                const uint32_t so  = off ^ ((off >> 3) & 0x70);
                ldmatrix_x2(Bhf[nt], bufB + so);
                if (TWOB) ldmatrix_x2(Blf[nt], bufB + 16384 + so);
            }
#pragma unroll
            for (int mt = 0; mt < 2; ++mt)
#pragma unroll
                for (int nt = 0; nt < 4; ++nt)
                    mma16816h(acc[mt][nt], Af[mt], Bhf[nt]);
            if (TWOB) {
#pragma unroll
                for (int mt = 0; mt < 2; ++mt)
#pragma unroll
                    for (int nt = 0; nt < 4; ++nt)
                        mma16816h(acc[mt][nt], Af[mt], Blf[nt]);
            }
        }
        __syncthreads();
        if (c + 4 < NCHUNK) issue_chunk(c + 4, buf);
        CP_COMMIT();
    }

#pragma unroll
    for (int mt = 0; mt < 2; ++mt) {
        const int r = m0 + wm * 32 + mt * 16 + (lane >> 2);
#pragma unroll
        for (int nt = 0; nt < 4; ++nt) {
            const int cc = n0 + wn * 32 + nt * 8 + (lane & 3) * 2;
            if (!SPLIT) {
                *(float2*)(C + (size_t)r * LDC + cc)       = make_float2(acc[mt][nt][0], acc[mt][nt][1]);
                *(float2*)(C + (size_t)(r + 8) * LDC + cc) = make_float2(acc[mt][nt][2], acc[mt][nt][3]);
            } else {
                uint32_t h, l;
                split2(acc[mt][nt][0] * premul, acc[mt][nt][1] * premul, h, l);
                *(uint32_t*)(Oh + (size_t)r * LDC + cc) = h;
                *(uint32_t*)(Ol + (size_t)r * LDC + cc) = l;
                split2(acc[mt][nt][2] * premul, acc[mt][nt][3] * premul, h, l);
                *(uint32_t*)(Oh + (size_t)(r + 8) * LDC + cc) = h;
                *(uint32_t*)(Ol + (size_t)(r + 8) * LDC + cc) = l;
            }
        }
    }
}

// ===========================================================================
// FA2-style HMMA attention (bf16 3-term). Emits fp16 single for O-projection.
// grid (LQ/128, B_*NH), 256 threads.
// ===========================================================================
#define AT_QH 0
#define AT_QL 16384
#define AT_KH 32768
#define AT_KL 43008
#define AT_VH 53248
#define AT_VL 64512
#define AT_SMEM 75776
#define VT_B  176

__global__ __launch_bounds__(256)
void attn_mma(const __nv_bfloat16* __restrict__ Qh, const __nv_bfloat16* __restrict__ Ql,
              const __nv_bfloat16* __restrict__ KVh, const __nv_bfloat16* __restrict__ KVl,
              __half* __restrict__ Oa)
{
    extern __shared__ char sm[];
    const uint32_t base = smem_u32(sm);
    const int tid  = threadIdx.x;
    const int w    = tid >> 5;
    const int lane = tid & 31;
    const int bh   = blockIdx.y;
    const int b    = bh >> 3;
    const int h    = bh & 7;
    const int qrow0 = b * LQ + blockIdx.x * 128;

    for (int i = tid; i < (AT_SMEM - AT_VH) / 4; i += 256)
        ((uint32_t*)(sm + AT_VH))[i] = 0;
    if (tid < 192) {
        const int lvl = tid / 96, rr = (tid % 96) / 32, c = tid % 32;
        *(uint32_t*)(sm + (lvl ? AT_KL : AT_KH) + (77 + rr) * 128 + c * 4) = 0;
    }

#pragma unroll
    for (int i = 0; i < 8; ++i) {
        const int idx = i * 256 + tid;
        const int lvl = idx >> 10;
        const int rem = idx & 1023;
        const int r = rem >> 3, c = rem & 7;
        const __nv_bfloat16* src = (lvl ? Ql : Qh) + (size_t)(qrow0 + r) * 512 + h * 64 + c * 8;
        cp_async16(base + (lvl ? AT_QL : AT_QH) + swz128((uint32_t)(r * 128 + c * 16)), src);
    }
#pragma unroll
    for (int i = 0; i < 5; ++i) {
        const int idx = i * 256 + tid;
        if (idx < 1232) {
            const int lvl = idx >= 616;
            const int rem = idx - lvl * 616;
            const int j = rem >> 3, c = rem & 7;
            const __nv_bfloat16* src = (lvl ? KVl : KVh) + (size_t)(b * LK + j) * 1024 + h * 64 + c * 8;
            cp_async16(base + (lvl ? AT_KL : AT_KH) + swz128((uint32_t)(j * 128 + c * 16)), src);
        }
    }
    CP_COMMIT();

    for (int idx = tid; idx < 2 * LK * 64; idx += 256) {
        const int lvl = idx >= LK * 64;
        const int rem = idx - lvl * LK * 64;
        const int j = rem >> 6, d = rem & 63;
        const __nv_bfloat16 v = (lvl ? KVl : KVh)[(size_t)(b * LK + j) * 1024 + 512 + h * 64 + d];
        *(__nv_bfloat16*)(sm + (lvl ? AT_VL : AT_VH) + d * VT_B + j * 2) = v;
    }
    CP_WAIT0();
    __syncthreads();

    float s[10][4];
#pragma unroll
    for (int nt = 0; nt < 10; ++nt)
#pragma unroll
        for (int q = 0; q < 4; ++q) s[nt][q] = 0.f;

    const uint32_t aBase = (uint32_t)((w * 16 + (lane & 15)) * 128 + (lane >> 4) * 16);
    const uint32_t bRowK = (uint32_t)(((lane & 7)) * 128 + ((lane >> 3) & 1) * 16);
#pragma unroll
    for (int kb = 0; kb < 4; ++kb) {
        const uint32_t ao = aBase + kb * 32;
        const uint32_t aso = ao ^ ((ao >> 3) & 0x70);
        uint32_t qhf[4], qlf[4];
        ldmatrix_x4(qhf, base + AT_QH + aso);
        ldmatrix_x4(qlf, base + AT_QL + aso);
#pragma unroll
        for (int nt = 0; nt < 10; ++nt) {
            const uint32_t bo = bRowK + nt * 8 * 128 + kb * 32;
            const uint32_t bso = bo ^ ((bo >> 3) & 0x70);
            uint32_t khf[2], klf[2];
            ldmatrix_x2(khf, base + AT_KH + bso);
            ldmatrix_x2(klf, base + AT_KL + bso);
            mma16816(s[nt], qhf, khf);
            mma16816(s[nt], qhf, klf);
            mma16816(s[nt], qlf, khf);
        }
    }

    const int t = lane & 3;
    if (t == 2) { s[9][1] = -1e30f; s[9][3] = -1e30f; }
    if (t == 3) { s[9][0] = -1e30f; s[9][1] = -1e30f; s[9][2] = -1e30f; s[9][3] = -1e30f; }

    float mlo = -1e30f, mhi = -1e30f;
#pragma unroll
    for (int nt = 0; nt < 10; ++nt) {
        mlo = fmaxf(mlo, fmaxf(s[nt][0], s[nt][1]));
        mhi = fmaxf(mhi, fmaxf(s[nt][2], s[nt][3]));
    }
#pragma unroll
    for (int o = 1; o <= 2; o <<= 1) {
        mlo = fmaxf(mlo, __shfl_xor_sync(0xffffffffu, mlo, o));
        mhi = fmaxf(mhi, __shfl_xor_sync(0xffffffffu, mhi, o));
    }
    float slo = 0.f, shi = 0.f;
#pragma unroll
    for (int nt = 0; nt < 10; ++nt) {
        s[nt][0] = __expf(s[nt][0] - mlo);
        s[nt][1] = __expf(s[nt][1] - mlo);
        s[nt][2] = __expf(s[nt][2] - mhi);
        s[nt][3] = __expf(s[nt][3] - mhi);
        slo += s[nt][0] + s[nt][1];
        shi += s[nt][2] + s[nt][3];
    }
#pragma unroll
    for (int o = 1; o <= 2; o <<= 1) {
        slo += __shfl_xor_sync(0xffffffffu, slo, o);
        shi += __shfl_xor_sync(0xffffffffu, shi, o);
    }
    const float rlo = 1.f / slo, rhi = 1.f / shi;

    float o[8][4];
#pragma unroll
    for (int dn = 0; dn < 8; ++dn)
#pragma unroll
        for (int q = 0; q < 4; ++q) o[dn][q] = 0.f;

    const uint32_t bRowV = (uint32_t)(((lane & 7)) * VT_B + ((lane >> 3) & 1) * 16);
#pragma unroll
    for (int kt = 0; kt < 5; ++kt) {
        uint32_t ph[4], pl[4];
        split2(s[2 * kt][0],     s[2 * kt][1],     ph[0], pl[0]);
        split2(s[2 * kt][2],     s[2 * kt][3],     ph[1], pl[1]);
        split2(s[2 * kt + 1][0], s[2 * kt + 1][1], ph[2], pl[2]);
        split2(s[2 * kt + 1][2], s[2 * kt + 1][3], ph[3], pl[3]);
#pragma unroll
        for (int dn = 0; dn < 8; ++dn) {
            const uint32_t bo = bRowV + dn * 8 * VT_B + kt * 32;
            uint32_t vhf[2], vlf[2];
            ldmatrix_x2(vhf, base + AT_VH + bo);
            ldmatrix_x2(vlf, base + AT_VL + bo);
            mma16816(o[dn], ph, vhf);
            mma16816(o[dn], ph, vlf);
            mma16816(o[dn], pl, vhf);
        }
    }

    const int g = lane >> 2;
    const size_t rA = (size_t)(qrow0 + w * 16 + g) * 512 + h * 64;
    const size_t rB = rA + 8 * 512;
#pragma unroll
    for (int dn = 0; dn < 8; ++dn) {
        const int col = dn * 8 + 2 * t;
        *(uint32_t*)(Oa + rA + col) = pack_h2(o[dn][0] * rlo, o[dn][1] * rlo);
        *(uint32_t*)(Oa + rB + col) = pack_h2(o[dn][2] * rhi, o[dn][3] * rhi);
    }
}

// ===========================================================================
extern "C" void kernel_launch(void* const* d_in, const int* in_sizes, int n_in,
                              void* d_out, int out_size)
{
    (void)in_sizes; (void)n_in; (void)out_size;
    const float* x    = (const float*)d_in[0];
    const float* cond = (const float*)d_in[1];
    const float* w_q  = (const float*)d_in[2];
    const float* w_k  = (const float*)d_in[3];
    const float* w_v  = (const float*)d_in[4];
    const float* w_o  = (const float*)d_in[5];
    float* out = (float*)d_out;

    __half *xh, *ch, *ah, *wqh, *woh, *wkvh, *wkvl;
    __nv_bfloat16 *qhi, *qlo, *kvhi, *kvlo;
    cudaGetSymbolAddress((void**)&xh, g_xh);
    cudaGetSymbolAddress((void**)&ch, g_ch);
    cudaGetSymbolAddress((void**)&ah, g_ah);
    cudaGetSymbolAddress((void**)&wqh, g_wqh);
    cudaGetSymbolAddress((void**)&woh, g_woh);
    cudaGetSymbolAddress((void**)&wkvh, g_wkvh); cudaGetSymbolAddress((void**)&wkvl, g_wkvl);
    cudaGetSymbolAddress((void**)&qhi, g_qhi);   cudaGetSymbolAddress((void**)&qlo, g_qlo);
    cudaGetSymbolAddress((void**)&kvhi, g_kvhi); cudaGetSymbolAddress((void**)&kvlo, g_kvlo);

    cudaFuncSetAttribute((void*)gemm_f16<512, 512, false, false>, cudaFuncAttributeMaxDynamicSharedMemorySize, GM_SMEM_1);
    cudaFuncSetAttribute((void*)gemm_f16<512, 512, true, false>,  cudaFuncAttributeMaxDynamicSharedMemorySize, GM_SMEM_1);
    cudaFuncSetAttribute((void*)gemm_f16<768, 1024, true, true>,  cudaFuncAttributeMaxDynamicSharedMemorySize, GM_SMEM_2);
    cudaFuncSetAttribute((void*)attn_mma, cudaFuncAttributeMaxDynamicSharedMemorySize, AT_SMEM);

    const int XN4 = B_ * LQ * DMODEL / 4;
    const int WN4 = DMODEL * INNER / 4;
    const int CN4 = MKV * DCOND / 4;
    const int WKN4 = INNER * DCOND / 4;
    // activations + big-GEMM weights: single fp16
    cvt_h<<<(XN4 + 255) / 256, 256>>>((const float4*)x, (uint2*)xh, XN4);
    cvt_h<<<(CN4 + 255) / 256, 256>>>((const float4*)cond, (uint2*)ch, CN4);
    cvt_h<<<(WN4 + 255) / 256, 256>>>((const float4*)w_q, (uint2*)wqh, WN4);
    cvt_h<<<(WN4 + 255) / 256, 256>>>((const float4*)w_o, (uint2*)woh, WN4);
    // K/V weights: 2-term (keeps direct V error out of the budget)
    cvt_h2<<<(WKN4 + 255) / 256, 256>>>((const float4*)w_k, (uint2*)wkvh, (uint2*)wkvl, WKN4);
    cvt_h2<<<(WKN4 + 255) / 256, 256>>>((const float4*)w_v,
        (uint2*)(wkvh + (size_t)INNER * DCOND), (uint2*)(wkvl + (size_t)INNER * DCOND), WKN4);

    // K+V projection (2-term B) -> bf16 hi/lo [MKVP,1024]
    gemm_f16<768, 1024, true, true><<<dim3(MKVP / 128, 8), 512, GM_SMEM_2>>>(
        ch, wkvh, wkvl, nullptr, kvhi, kvlo, 1.f);

    // Q projection (single x single) -> bf16 hi/lo, pre-scaled 1/sqrt(64)
    gemm_f16<512, 512, true, false><<<dim3(512, 4), 512, GM_SMEM_1>>>(
        xh, wqh, nullptr, nullptr, qhi, qlo, 0.125f);

    // Tensor-core attention -> fp16 single
    attn_mma<<<dim3(LQ / 128, B_ * NH), 256, AT_SMEM>>>(qhi, qlo, kvhi, kvlo, ah);

    // Output projection (single x single) -> fp32
    gemm_f16<512, 512, false, false><<<dim3(512, 4), 512, GM_SMEM_1>>>(
        ah, woh, nullptr, out, nullptr, nullptr, 1.f);
}

// round 12
// speedup vs baseline: 5.0551x; 1.0560x over previous
#include <cuda_runtime.h>
#include <cuda_fp16.h>
#include <cstdint>
#include <math.h>

#define B_     16
#define LQ     4096
#define LK     77
#define DMODEL 512
#define DCOND  768
#define NH     8
#define HD     64
#define INNER  512   // NH*HD
#define MKV    1232  // B_*LK
#define MKVP   1280  // padded to 128

// Scratch (allocation-free rule: __device__ globals; zero-initialized)
__device__ __half g_ch[MKVP * DCOND];                 // cond fp16 (pad rows 0)
__device__ __half g_ah[(size_t)B_ * LQ * INNER];      // attention out fp16
__device__ __half g_qh[(size_t)B_ * LQ * INNER];      // Q*0.125 fp16 single
__device__ __half g_wqh[DMODEL * INNER];              // w_q single fp16
__device__ __half g_woh[DMODEL * INNER];              // w_o single fp16
__device__ __half g_wkvh[2 * INNER * DCOND];          // [w_k ; w_v] 2-term
__device__ __half g_wkvl[2 * INNER * DCOND];
__device__ __half g_kvh[(size_t)MKVP * 1024];         // K cols 0..511, V 512..1023
__device__ __half g_kvl[(size_t)MKVP * 1024];         // fp16 residuals

// ===========================================================================
// Helpers (base PTX only)
// ===========================================================================
__device__ __forceinline__ uint32_t smem_u32(const void* p) {
    uint32_t a;
    asm("{ .reg .u64 t; cvta.to.shared.u64 t, %1; cvt.u32.u64 %0, t; }" : "=r"(a) : "l"(p));
    return a;
}
__device__ __forceinline__ uint32_t swz128(uint32_t off) { return off ^ ((off >> 3) & 0x70); }

__device__ __forceinline__ void ldmatrix_x4(uint32_t* r, uint32_t addr) {
    asm volatile("ldmatrix.sync.aligned.m8n8.x4.shared.b16 {%0,%1,%2,%3}, [%4];"
        : "=r"(r[0]), "=r"(r[1]), "=r"(r[2]), "=r"(r[3]) : "r"(addr));
}
__device__ __forceinline__ void ldmatrix_x2(uint32_t* r, uint32_t addr) {
    asm volatile("ldmatrix.sync.aligned.m8n8.x2.shared.b16 {%0,%1}, [%2];"
        : "=r"(r[0]), "=r"(r[1]) : "r"(addr));
}
// fp16 MMA
__device__ __forceinline__ void mma16816h(float* d, const uint32_t* a, const uint32_t* b) {
    asm volatile("mma.sync.aligned.m16n8k16.row.col.f32.f16.f16.f32 "
        "{%0,%1,%2,%3}, {%4,%5,%6,%7}, {%8,%9}, {%0,%1,%2,%3};"
        : "+f"(d[0]), "+f"(d[1]), "+f"(d[2]), "+f"(d[3])
        : "r"(a[0]), "r"(a[1]), "r"(a[2]), "r"(a[3]), "r"(b[0]), "r"(b[1]));
}
__device__ __forceinline__ void cp_async16(uint32_t dst, const void* src) {
    asm volatile("cp.async.cg.shared.global [%0], [%1], 16;" :: "r"(dst), "l"(src));
}
#define CP_COMMIT() asm volatile("cp.async.commit_group;" ::: "memory")
#define CP_WAIT3()  asm volatile("cp.async.wait_group 3;" ::: "memory")
#define CP_WAIT0()  asm volatile("cp.async.wait_group 0;" ::: "memory")

__device__ __forceinline__ uint32_t pack_h2(float x, float y) {
    __half2 h = __floats2half2_rn(x, y);
    return *(const uint32_t*)&h;
}
// split two floats into packed fp16x2 hi + residual lo
__device__ __forceinline__ void split2h(float x, float y, uint32_t& hi, uint32_t& lo) {
    const __half hx = __float2half_rn(x), hy = __float2half_rn(y);
    hi = (uint32_t)__half_as_ushort(hx) | ((uint32_t)__half_as_ushort(hy) << 16);
    lo = pack_h2(x - __half2float(hx), y - __half2float(hy));
}

// fp32 -> single fp16
__global__ void cvt_h(const float4* __restrict__ in, uint2* __restrict__ out, int n4)
{
    const int i = blockIdx.x * blockDim.x + threadIdx.x;
    if (i >= n4) return;
    const float4 v = in[i];
    out[i] = make_uint2(pack_h2(v.x, v.y), pack_h2(v.z, v.w));
}
// fp32 -> fp16 hi + residual lo
__global__ void cvt_h2(const float4* __restrict__ in, uint2* __restrict__ hi,
                       uint2* __restrict__ lo, int n4)
{
    const int i = blockIdx.x * blockDim.x + threadIdx.x;
    if (i >= n4) return;
    const float4 v = in[i];
    uint32_t h0, l0, h1, l1;
    split2h(v.x, v.y, h0, l0);
    split2h(v.z, v.w, h1, l1);
    hi[i] = make_uint2(h0, h1);
    lo[i] = make_uint2(l0, l1);
}

// ===========================================================================
// fp16 HMMA GEMM. 128x128 tile, K-chunk 64, 512 thr (16 warps 4x4, 32x32 warp).
// AF32: A read as fp32 via LDG + inline convert (double-buffered A smem);
//       else A fp16 via cp.async in-stage.
// TWOB: B = Bh + Bl (2 MMAs/k16) else single B.
// OUT:  0 = fp32 C; 1 = fp16 single (premul); 2 = fp16 hi/lo split (premul).
// ===========================================================================
#define SM_Q  (2 * 16384 + 4 * 16384)   // AF32 path: 98304
#define SM_O  (4 * 32768)               // fp16 A, 1B: 131072
#define SM_KV (4 * 49152)               // fp16 A, 2B: 196608

template <int KDIM, int LDC, int OUT, bool AF32, bool TWOB>
__global__ void __launch_bounds__(512, 1)
gemm_f16(const __half* __restrict__ A, const float* __restrict__ Af,
         const __half* __restrict__ Bh, const __half* __restrict__ Bl,
         float* __restrict__ C, __half* __restrict__ Oh, __half* __restrict__ Ol,
         float premul)
{
    constexpr int NCHUNK = KDIM / 64;
    constexpr int STAGE  = TWOB ? 49152 : 32768;   // non-AF32 stage size
    extern __shared__ char sm[];
    const uint32_t base = smem_u32(sm);
    const int tid  = threadIdx.x;
    const int wid  = tid >> 5;
    const int lane = tid & 31;
    const int wm   = wid & 3;
    const int wn   = wid >> 2;

    const int m0 = blockIdx.x * 128;
    const int n0 = blockIdx.y * 128;
    const __half* A0  = AF32 ? nullptr : (A + (size_t)m0 * KDIM);
    const float*  Af0 = AF32 ? (Af + (size_t)m0 * KDIM) : nullptr;
    const __half* Bh0 = Bh + (size_t)n0 * KDIM;
    const __half* Bl0 = TWOB ? (Bl + (size_t)n0 * KDIM) : nullptr;

    float acc[2][4][4];
#pragma unroll
    for (int mt = 0; mt < 2; ++mt)
#pragma unroll
        for (int nt = 0; nt < 4; ++nt)
#pragma unroll
            for (int q = 0; q < 4; ++q) acc[mt][nt][q] = 0.f;

    uint32_t aRow0[2], bRow0[4];
#pragma unroll
    for (int mt = 0; mt < 2; ++mt)
        aRow0[mt] = (uint32_t)((wm * 32 + mt * 16 + (lane & 15)) * 128 + (lane >> 4) * 16);
#pragma unroll
    for (int nt = 0; nt < 4; ++nt)
        bRow0[nt] = (uint32_t)((wn * 32 + nt * 8 + (lane & 7)) * 128 + ((lane >> 3) & 1) * 16);

    // ---- AF32 A-path state ----
    float4 ar[4];
    auto ldA = [&](int c) {
        const int kc = c * 64;
#pragma unroll
        for (int t = 0; t < 2; ++t) {
            const int idx = t * 512 + tid;     // 0..1023 (16B fp16 groups)
            const int row = idx >> 3;
            const int c8  = idx & 7;
            const float* p = Af0 + (size_t)row * KDIM + kc + c8 * 8;
            ar[2 * t]     = *(const float4*)p;
            ar[2 * t + 1] = *(const float4*)(p + 4);
        }
    };
    auto stA = [&](int abuf) {
#pragma unroll
        for (int t = 0; t < 2; ++t) {
            const int idx = t * 512 + tid;
            const int row = idx >> 3;
            const int c8  = idx & 7;
            uint4 v;
            v.x = pack_h2(ar[2 * t].x,     ar[2 * t].y);
            v.y = pack_h2(ar[2 * t].z,     ar[2 * t].w);
            v.z = pack_h2(ar[2 * t + 1].x, ar[2 * t + 1].y);
            v.w = pack_h2(ar[2 * t + 1].z, ar[2 * t + 1].w);
            *(uint4*)(sm + abuf * 16384 + swz128((uint32_t)(row * 128 + c8 * 16))) = v;
        }
    };
    auto issueB_af32 = [&](int c) {
        const int kc = c * 64;
        const uint32_t tb = base + 32768 + (c & 3) * 16384;
#pragma unroll
        for (int t = 0; t < 2; ++t) {
            const int idx = t * 512 + tid;
            const int row = idx >> 3;
            const int c8  = idx & 7;
            cp_async16(tb + swz128((uint32_t)(row * 128 + c8 * 16)),
                       Bh0 + (size_t)row * KDIM + kc + c8 * 8);
        }
    };
    // ---- non-AF32 combined stage loader ----
    auto issue_chunk = [&](int c, int buf) {
        const int kc = c * 64;
        const uint32_t tb = base + buf * STAGE;
#pragma unroll
        for (int i = 0; i < 2; ++i) {
            const int idx = i * 512 + tid;
            const int row = idx >> 3;
            const int c8  = idx & 7;
            const uint32_t so = swz128((uint32_t)(row * 128 + c8 * 16));
            const size_t go = (size_t)row * KDIM + kc + c8 * 8;
            cp_async16(tb + so,         A0  + go);
            cp_async16(tb + 16384 + so, Bh0 + go);
            if (TWOB) cp_async16(tb + 32768 + so, Bl0 + go);
        }
    };

    if (AF32) {
        ldA(0);
        issueB_af32(0); CP_COMMIT();
        issueB_af32(1); CP_COMMIT();
        issueB_af32(2); CP_COMMIT();
        issueB_af32(3); CP_COMMIT();
    } else {
        issue_chunk(0, 0); CP_COMMIT();
        issue_chunk(1, 1); CP_COMMIT();
        issue_chunk(2, 2); CP_COMMIT();
        issue_chunk(3, 3); CP_COMMIT();
    }

    for (int c = 0; c < NCHUNK; ++c) {
        CP_WAIT3();
        __syncthreads();

        uint32_t bufA, bufB;
        if (AF32) {
            stA(c & 1);
            if (c + 1 < NCHUNK) ldA(c + 1);
            __syncthreads();
            bufA = base + (c & 1) * 16384;
            bufB = base + 32768 + (c & 3) * 16384;
        } else {
            bufA = base + (c & 3) * STAGE;
            bufB = bufA + 16384;
        }

#pragma unroll
        for (int kb = 0; kb < 4; ++kb) {
            const uint32_t kbyte = kb * 32;
            uint32_t Afr[2][4], Bhf[4][2], Blf[4][2];
#pragma unroll
            for (int mt = 0; mt < 2; ++mt) {
                const uint32_t off = aRow0[mt] + kbyte;
                ldmatrix_x4(Afr[mt], bufA + (off ^ ((off >> 3) & 0x70)));
            }
#pragma unroll
            for (int nt = 0; nt < 4; ++nt) {
                const uint32_t off = bRow0[nt] + kbyte;
                const uint32_t so  = off ^ ((off >> 3) & 0x70);
                ldmatrix_x2(Bhf[nt], bufB + so);
                if (TWOB) ldmatrix_x2(Blf[nt], bufB + 16384 + so);
            }
#pragma unroll
            for (int mt = 0; mt < 2; ++mt)
#pragma unroll
                for (int nt = 0; nt < 4; ++nt)
                    mma16816h(acc[mt][nt], Afr[mt], Bhf[nt]);
            if (TWOB) {
#pragma unroll
                for (int mt = 0; mt < 2; ++mt)
#pragma unroll
                    for (int nt = 0; nt < 4; ++nt)
                        mma16816h(acc[mt][nt], Afr[mt], Blf[nt]);
            }
        }
        __syncthreads();
        if (c + 4 < NCHUNK) {
            if (AF32) issueB_af32(c + 4);
            else      issue_chunk(c + 4, (c + 4) & 3);
        }
        CP_COMMIT();
    }

#pragma unroll
    for (int mt = 0; mt < 2; ++mt) {
        const int r = m0 + wm * 32 + mt * 16 + (lane >> 2);
#pragma unroll
        for (int nt = 0; nt < 4; ++nt) {
            const int cc = n0 + wn * 32 + nt * 8 + (lane & 3) * 2;
            if (OUT == 0) {
                *(float2*)(C + (size_t)r * LDC + cc)       = make_float2(acc[mt][nt][0], acc[mt][nt][1]);
                *(float2*)(C + (size_t)(r + 8) * LDC + cc) = make_float2(acc[mt][nt][2], acc[mt][nt][3]);
            } else if (OUT == 1) {
                *(uint32_t*)(Oh + (size_t)r * LDC + cc)       = pack_h2(acc[mt][nt][0] * premul, acc[mt][nt][1] * premul);
                *(uint32_t*)(Oh + (size_t)(r + 8) * LDC + cc) = pack_h2(acc[mt][nt][2] * premul, acc[mt][nt][3] * premul);
            } else {
                uint32_t h, l;
                split2h(acc[mt][nt][0] * premul, acc[mt][nt][1] * premul, h, l);
                *(uint32_t*)(Oh + (size_t)r * LDC + cc) = h;
                *(uint32_t*)(Ol + (size_t)r * LDC + cc) = l;
                split2h(acc[mt][nt][2] * premul, acc[mt][nt][3] * premul, h, l);
                *(uint32_t*)(Oh + (size_t)(r + 8) * LDC + cc) = h;
                *(uint32_t*)(Ol + (size_t)(r + 8) * LDC + cc) = l;
            }
        }
    }
}

// ===========================================================================
// FA2-style fp16 HMMA attention: Q single, K/V 2-term (4 MMA-sets per step).
// grid (LQ/128, B_*NH), 256 threads. Emits fp16 single for O-projection.
// ===========================================================================
#define AQ  0
#define AKH 16384
#define AKL 26624
#define AVH 36864
#define AVL 48128
#define AT_SMEM 59392
#define VT_B 176

__global__ __launch_bounds__(256)
void attn_mma(const __half* __restrict__ Q, const __half* __restrict__ KVh,
              const __half* __restrict__ KVl, __half* __restrict__ Oa)
{
    extern __shared__ char sm[];
    const uint32_t base = smem_u32(sm);
    const int tid  = threadIdx.x;
    const int w    = tid >> 5;
    const int lane = tid & 31;
    const int bh   = blockIdx.y;
    const int b    = bh >> 3;
    const int h    = bh & 7;
    const int qrow0 = b * LQ + blockIdx.x * 128;

    // zero V region (incl. j-pad) and K pad rows 77..79 (both levels)
    for (int i = tid; i < (AT_SMEM - AVH) / 4; i += 256)
        ((uint32_t*)(sm + AVH))[i] = 0;
    if (tid < 192) {
        const int lvl = tid / 96, rr = (tid % 96) / 32, c = tid % 32;
        *(uint32_t*)(sm + (lvl ? AKL : AKH) + (77 + rr) * 128 + c * 4) = 0;
    }

    // Q: 128 rows x 8 16B-chunks
#pragma unroll
    for (int i = 0; i < 4; ++i) {
        const int idx = i * 256 + tid;         // 0..1023
        const int r = idx >> 3, c = idx & 7;
        cp_async16(base + AQ + swz128((uint32_t)(r * 128 + c * 16)),
                   Q + (size_t)(qrow0 + r) * 512 + h * 64 + c * 8);
    }
    // K: 77 rows x 8 chunks x 2 levels
#pragma unroll
    for (int i = 0; i < 5; ++i) {
        const int idx = i * 256 + tid;
        if (idx < 1232) {
            const int lvl = idx >= 616;
            const int rem = idx - lvl * 616;
            const int j = rem >> 3, c = rem & 7;
            cp_async16(base + (lvl ? AKL : AKH) + swz128((uint32_t)(j * 128 + c * 16)),
                       (lvl ? KVl : KVh) + (size_t)(b * LK + j) * 1024 + h * 64 + c * 8);
        }
    }
    CP_COMMIT();

    // scalar transpose V -> VT [d][j], both levels
    for (int idx = tid; idx < 2 * LK * 64; idx += 256) {
        const int lvl = idx >= LK * 64;
        const int rem = idx - lvl * LK * 64;
        const int j = rem >> 6, d = rem & 63;
        const __half v = (lvl ? KVl : KVh)[(size_t)(b * LK + j) * 1024 + 512 + h * 64 + d];
        *(__half*)(sm + (lvl ? AVL : AVH) + d * VT_B + j * 2) = v;
    }
    CP_WAIT0();
    __syncthreads();

    // ---- S = Q K^T (Q single, K 2-term), 10 n8 tiles ----
    float s[10][4];
#pragma unroll
    for (int nt = 0; nt < 10; ++nt)
#pragma unroll
        for (int q = 0; q < 4; ++q) s[nt][q] = 0.f;

    const uint32_t aBase = (uint32_t)((w * 16 + (lane & 15)) * 128 + (lane >> 4) * 16);
    const uint32_t bRowK = (uint32_t)(((lane & 7)) * 128 + ((lane >> 3) & 1) * 16);
#pragma unroll
    for (int kb = 0; kb < 4; ++kb) {
        const uint32_t ao = aBase + kb * 32;
        uint32_t qf[4];
        ldmatrix_x4(qf, base + AQ + (ao ^ ((ao >> 3) & 0x70)));
#pragma unroll
        for (int nt = 0; nt < 10; ++nt) {
            const uint32_t bo = bRowK + nt * 8 * 128 + kb * 32;
            const uint32_t bso = bo ^ ((bo >> 3) & 0x70);
            uint32_t khf[2], klf[2];
            ldmatrix_x2(khf, base + AKH + bso);
            ldmatrix_x2(klf, base + AKL + bso);
            mma16816h(s[nt], qf, khf);
            mma16816h(s[nt], qf, klf);
        }
    }

    // mask j >= 77 (tile nt=9)
    const int t = lane & 3;
    if (t == 2) { s[9][1] = -1e30f; s[9][3] = -1e30f; }
    if (t == 3) { s[9][0] = -1e30f; s[9][1] = -1e30f; s[9][2] = -1e30f; s[9][3] = -1e30f; }

    // ---- softmax on fragments ----
    float mlo = -1e30f, mhi = -1e30f;
#pragma unroll
    for (int nt = 0; nt < 10; ++nt) {
        mlo = fmaxf(mlo, fmaxf(s[nt][0], s[nt][1]));
        mhi = fmaxf(mhi, fmaxf(s[nt][2], s[nt][3]));
    }
#pragma unroll
    for (int o = 1; o <= 2; o <<= 1) {
        mlo = fmaxf(mlo, __shfl_xor_sync(0xffffffffu, mlo, o));
        mhi = fmaxf(mhi, __shfl_xor_sync(0xffffffffu, mhi, o));
    }
    float slo = 0.f, shi = 0.f;
#pragma unroll
    for (int nt = 0; nt < 10; ++nt) {
        s[nt][0] = __expf(s[nt][0] - mlo);
        s[nt][1] = __expf(s[nt][1] - mlo);
        s[nt][2] = __expf(s[nt][2] - mhi);
        s[nt][3] = __expf(s[nt][3] - mhi);
        slo += s[nt][0] + s[nt][1];
        shi += s[nt][2] + s[nt][3];
    }
#pragma unroll
    for (int o = 1; o <= 2; o <<= 1) {
        slo += __shfl_xor_sync(0xffffffffu, slo, o);
        shi += __shfl_xor_sync(0xffffffffu, shi, o);
    }
    const float rlo = 1.f / slo, rhi = 1.f / shi;

    // ---- O = P V (P single fp16, V 2-term) ----
    float o[8][4];
#pragma unroll
    for (int dn = 0; dn < 8; ++dn)
#pragma unroll
        for (int q = 0; q < 4; ++q) o[dn][q] = 0.f;

    const uint32_t bRowV = (uint32_t)(((lane & 7)) * VT_B + ((lane >> 3) & 1) * 16);
#pragma unroll
    for (int kt = 0; kt < 5; ++kt) {
        uint32_t p[4];
        p[0] = pack_h2(s[2 * kt][0],     s[2 * kt][1]);
        p[1] = pack_h2(s[2 * kt][2],     s[2 * kt][3]);
        p[2] = pack_h2(s[2 * kt + 1][0], s[2 * kt + 1][1]);
        p[3] = pack_h2(s[2 * kt + 1][2], s[2 * kt + 1][3]);
#pragma unroll
        for (int dn = 0; dn < 8; ++dn) {
            const uint32_t bo = bRowV + dn * 8 * VT_B + kt * 32;
            uint32_t vhf[2], vlf[2];
            ldmatrix_x2(vhf, base + AVH + bo);
            ldmatrix_x2(vlf, base + AVL + bo);
            mma16816h(o[dn], p, vhf);
            mma16816h(o[dn], p, vlf);
        }
    }

    const int g = lane >> 2;
    const size_t rA = (size_t)(qrow0 + w * 16 + g) * 512 + h * 64;
    const size_t rB = rA + 8 * 512;
#pragma unroll
    for (int dn = 0; dn < 8; ++dn) {
        const int col = dn * 8 + 2 * t;
        *(uint32_t*)(Oa + rA + col) = pack_h2(o[dn][0] * rlo, o[dn][1] * rlo);
        *(uint32_t*)(Oa + rB + col) = pack_h2(o[dn][2] * rhi, o[dn][3] * rhi);
    }
}

// ===========================================================================
extern "C" void kernel_launch(void* const* d_in, const int* in_sizes, int n_in,
                              void* d_out, int out_size)
{
    (void)in_sizes; (void)n_in; (void)out_size;
    const float* x    = (const float*)d_in[0];
    const float* cond = (const float*)d_in[1];
    const float* w_q  = (const float*)d_in[2];
    const float* w_k  = (const float*)d_in[3];
    const float* w_v  = (const float*)d_in[4];
    const float* w_o  = (const float*)d_in[5];
    float* out = (float*)d_out;

    __half *ch, *ah, *qh, *wqh, *woh, *wkvh, *wkvl, *kvh, *kvl;
    cudaGetSymbolAddress((void**)&ch, g_ch);
    cudaGetSymbolAddress((void**)&ah, g_ah);
    cudaGetSymbolAddress((void**)&qh, g_qh);
    cudaGetSymbolAddress((void**)&wqh, g_wqh);
    cudaGetSymbolAddress((void**)&woh, g_woh);
    cudaGetSymbolAddress((void**)&wkvh, g_wkvh); cudaGetSymbolAddress((void**)&wkvl, g_wkvl);
    cudaGetSymbolAddress((void**)&kvh, g_kvh);   cudaGetSymbolAddress((void**)&kvl, g_kvl);

    cudaFuncSetAttribute((void*)gemm_f16<512, 512, 1, true, false>,  cudaFuncAttributeMaxDynamicSharedMemorySize, SM_Q);
    cudaFuncSetAttribute((void*)gemm_f16<512, 512, 0, false, false>, cudaFuncAttributeMaxDynamicSharedMemorySize, SM_O);
    cudaFuncSetAttribute((void*)gemm_f16<768, 1024, 2, false, true>, cudaFuncAttributeMaxDynamicSharedMemorySize, SM_KV);
    cudaFuncSetAttribute((void*)attn_mma, cudaFuncAttributeMaxDynamicSharedMemorySize, AT_SMEM);

    const int WN4 = DMODEL * INNER / 4;
    const int CN4 = MKV * DCOND / 4;
    const int WKN4 = INNER * DCOND / 4;
    cvt_h<<<(CN4 + 255) / 256, 256>>>((const float4*)cond, (uint2*)ch, CN4);
    cvt_h<<<(WN4 + 255) / 256, 256>>>((const float4*)w_q, (uint2*)wqh, WN4);
    cvt_h<<<(WN4 + 255) / 256, 256>>>((const float4*)w_o, (uint2*)woh, WN4);
    cvt_h2<<<(WKN4 + 255) / 256, 256>>>((const float4*)w_k, (uint2*)wkvh, (uint2*)wkvl, WKN4);
    cvt_h2<<<(WKN4 + 255) / 256, 256>>>((const float4*)w_v,
        (uint2*)(wkvh + (size_t)INNER * DCOND), (uint2*)(wkvl + (size_t)INNER * DCOND), WKN4);

    // K+V projection (2-term B) -> fp16 hi/lo [MKVP,1024]
    gemm_f16<768, 1024, 2, false, true><<<dim3(MKVP / 128, 8), 512, SM_KV>>>(
        ch, nullptr, wkvh, wkvl, nullptr, kvh, kvl, 1.f);

    // Q projection: fp32 x inline-converted, single fp16 out (pre-scaled 0.125)
    gemm_f16<512, 512, 1, true, false><<<dim3(512, 4), 512, SM_Q>>>(
        nullptr, x, wqh, nullptr, nullptr, qh, nullptr, 0.125f);

    // fp16 tensor-core attention -> fp16 single
    attn_mma<<<dim3(LQ / 128, B_ * NH), 256, AT_SMEM>>>(qh, kvh, kvl, ah);

    // Output projection -> fp32
    gemm_f16<512, 512, 0, false, false><<<dim3(512, 4), 512, SM_O>>>(
        ah, nullptr, woh, nullptr, out, nullptr, nullptr, 1.f);
}

// round 13
// speedup vs baseline: 5.2439x; 1.0374x over previous
#include <cuda_runtime.h>
#include <cuda_fp16.h>
#include <cstdint>
#include <math.h>

#define B_     16
#define LQ     4096
#define LK     77
#define DMODEL 512
#define DCOND  768
#define NH     8
#define HD     64
#define INNER  512   // NH*HD
#define MKV    1232  // B_*LK
#define MKVP   1280  // padded to 128

// Scratch (allocation-free rule: __device__ globals; zero-initialized)
__device__ __half g_xh[(size_t)B_ * LQ * DMODEL];     // x fp16
__device__ __half g_ch[MKVP * DCOND];                 // cond fp16 (pad rows 0)
__device__ __half g_ah[(size_t)B_ * LQ * INNER];      // attention out fp16
__device__ __half g_qh[(size_t)B_ * LQ * INNER];      // Q*0.125 fp16 single
__device__ __half g_wqh[DMODEL * INNER];              // w_q single fp16
__device__ __half g_woh[DMODEL * INNER];              // w_o single fp16
__device__ __half g_wkvh[2 * INNER * DCOND];          // [w_k ; w_v] 2-term
__device__ __half g_wkvl[2 * INNER * DCOND];
__device__ __half g_kvh[(size_t)MKVP * 1024];         // K cols 0..511, V 512..1023
__device__ __half g_kvl[(size_t)MKVP * 1024];         // fp16 residuals

// ===========================================================================
// Helpers (base PTX only)
// ===========================================================================
__device__ __forceinline__ uint32_t smem_u32(const void* p) {
    uint32_t a;
    asm("{ .reg .u64 t; cvta.to.shared.u64 t, %1; cvt.u32.u64 %0, t; }" : "=r"(a) : "l"(p));
    return a;
}
__device__ __forceinline__ uint32_t swz128(uint32_t off) { return off ^ ((off >> 3) & 0x70); }

__device__ __forceinline__ void ldmatrix_x4(uint32_t* r, uint32_t addr) {
    asm volatile("ldmatrix.sync.aligned.m8n8.x4.shared.b16 {%0,%1,%2,%3}, [%4];"
        : "=r"(r[0]), "=r"(r[1]), "=r"(r[2]), "=r"(r[3]) : "r"(addr));
}
__device__ __forceinline__ void ldmatrix_x2(uint32_t* r, uint32_t addr) {
    asm volatile("ldmatrix.sync.aligned.m8n8.x2.shared.b16 {%0,%1}, [%2];"
        : "=r"(r[0]), "=r"(r[1]) : "r"(addr));
}
// fp16 MMA, fp32 accum
__device__ __forceinline__ void mma16816h(float* d, const uint32_t* a, const uint32_t* b) {
    asm volatile("mma.sync.aligned.m16n8k16.row.col.f32.f16.f16.f32 "
        "{%0,%1,%2,%3}, {%4,%5,%6,%7}, {%8,%9}, {%0,%1,%2,%3};"
        : "+f"(d[0]), "+f"(d[1]), "+f"(d[2]), "+f"(d[3])
        : "r"(a[0]), "r"(a[1]), "r"(a[2]), "r"(a[3]), "r"(b[0]), "r"(b[1]));
}
// fp16 MMA, fp16 accum (rate experiment)
__device__ __forceinline__ void mma16816hh(uint32_t* d, const uint32_t* a, const uint32_t* b) {
    asm volatile("mma.sync.aligned.m16n8k16.row.col.f16.f16.f16.f16 "
        "{%0,%1}, {%2,%3,%4,%5}, {%6,%7}, {%0,%1};"
        : "+r"(d[0]), "+r"(d[1])
        : "r"(a[0]), "r"(a[1]), "r"(a[2]), "r"(a[3]), "r"(b[0]), "r"(b[1]));
}
__device__ __forceinline__ void cp_async16(uint32_t dst, const void* src) {
    asm volatile("cp.async.cg.shared.global [%0], [%1], 16;" :: "r"(dst), "l"(src));
}
#define CP_COMMIT() asm volatile("cp.async.commit_group;" ::: "memory")
#define CP_WAIT3()  asm volatile("cp.async.wait_group 3;" ::: "memory")
#define CP_WAIT0()  asm volatile("cp.async.wait_group 0;" ::: "memory")

__device__ __forceinline__ uint32_t pack_h2(float x, float y) {
    __half2 h = __floats2half2_rn(x, y);
    return *(const uint32_t*)&h;
}
__device__ __forceinline__ void split2h(float x, float y, uint32_t& hi, uint32_t& lo) {
    const __half hx = __float2half_rn(x), hy = __float2half_rn(y);
    hi = (uint32_t)__half_as_ushort(hx) | ((uint32_t)__half_as_ushort(hy) << 16);
    lo = pack_h2(x - __half2float(hx), y - __half2float(hy));
}

// fp32 -> single fp16
__global__ void cvt_h(const float4* __restrict__ in, uint2* __restrict__ out, int n4)
{
    const int i = blockIdx.x * blockDim.x + threadIdx.x;
    if (i >= n4) return;
    const float4 v = in[i];
    out[i] = make_uint2(pack_h2(v.x, v.y), pack_h2(v.z, v.w));
}
// fp32 -> fp16 hi + residual lo
__global__ void cvt_h2(const float4* __restrict__ in, uint2* __restrict__ hi,
                       uint2* __restrict__ lo, int n4)
{
    const int i = blockIdx.x * blockDim.x + threadIdx.x;
    if (i >= n4) return;
    const float4 v = in[i];
    uint32_t h0, l0, h1, l1;
    split2h(v.x, v.y, h0, l0);
    split2h(v.z, v.w, h1, l1);
    hi[i] = make_uint2(h0, h1);
    lo[i] = make_uint2(l0, l1);
}

// ===========================================================================
// fp16 HMMA GEMM. 128x128 tile, K-chunk 64, 4-stage cp.async, 512 thr, 32x32 warp.
// TWOB: B = Bh + Bl (2 MMAs/k16). HACC: fp16 accumulators within a k64 chunk,
// promoted to fp32 per chunk (tests the f16-accum HMMA rate).
// OUT: 0 = fp32 C; 1 = fp16 single (premul); 2 = fp16 hi/lo split (premul).
// ===========================================================================
#define SM_1B (4 * 32768)
#define SM_2B (4 * 49152)

template <int KDIM, int LDC, int OUT, bool TWOB, bool HACC>
__global__ void __launch_bounds__(512, 1)
gemm_f16(const __half* __restrict__ A, const __half* __restrict__ Bh,
         const __half* __restrict__ Bl, float* __restrict__ C,
         __half* __restrict__ Oh, __half* __restrict__ Ol, float premul)
{
    constexpr int NCHUNK = KDIM / 64;
    constexpr int STAGE  = TWOB ? 49152 : 32768;
    extern __shared__ char sm[];
    const uint32_t base = smem_u32(sm);
    const int tid  = threadIdx.x;
    const int wid  = tid >> 5;
    const int lane = tid & 31;
    const int wm   = wid & 3;
    const int wn   = wid >> 2;

    const int m0 = blockIdx.x * 128;
    const int n0 = blockIdx.y * 128;
    const __half* A0  = A + (size_t)m0 * KDIM;
    const __half* Bh0 = Bh + (size_t)n0 * KDIM;
    const __half* Bl0 = TWOB ? (Bl + (size_t)n0 * KDIM) : nullptr;

    float acc[2][4][4];
#pragma unroll
    for (int mt = 0; mt < 2; ++mt)
#pragma unroll
        for (int nt = 0; nt < 4; ++nt)
#pragma unroll
            for (int q = 0; q < 4; ++q) acc[mt][nt][q] = 0.f;

    uint32_t aRow0[2], bRow0[4];
#pragma unroll
    for (int mt = 0; mt < 2; ++mt)
        aRow0[mt] = (uint32_t)((wm * 32 + mt * 16 + (lane & 15)) * 128 + (lane >> 4) * 16);
#pragma unroll
    for (int nt = 0; nt < 4; ++nt)
        bRow0[nt] = (uint32_t)((wn * 32 + nt * 8 + (lane & 7)) * 128 + ((lane >> 3) & 1) * 16);

    auto issue_chunk = [&](int c, int buf) {
        const int kc = c * 64;
        const uint32_t tb = base + buf * STAGE;
#pragma unroll
        for (int i = 0; i < 2; ++i) {
            const int idx = i * 512 + tid;
            const int row = idx >> 3;
            const int c8  = idx & 7;
            const uint32_t so = swz128((uint32_t)(row * 128 + c8 * 16));
            const size_t go = (size_t)row * KDIM + kc + c8 * 8;
            cp_async16(tb + so,         A0  + go);
            cp_async16(tb + 16384 + so, Bh0 + go);
            if (TWOB) cp_async16(tb + 32768 + so, Bl0 + go);
        }
    };

    issue_chunk(0, 0); CP_COMMIT();
    issue_chunk(1, 1); CP_COMMIT();
    issue_chunk(2, 2); CP_COMMIT();
    issue_chunk(3, 3); CP_COMMIT();

    for (int c = 0; c < NCHUNK; ++c) {
        const int buf = c & 3;
        CP_WAIT3();
        __syncthreads();

        const uint32_t bufA = base + buf * STAGE;
        const uint32_t bufB = bufA + 16384;

        uint32_t hacc[2][4][2];
        if (HACC) {
#pragma unroll
            for (int mt = 0; mt < 2; ++mt)
#pragma unroll
                for (int nt = 0; nt < 4; ++nt) { hacc[mt][nt][0] = 0; hacc[mt][nt][1] = 0; }
        }

#pragma unroll
        for (int kb = 0; kb < 4; ++kb) {
            const uint32_t kbyte = kb * 32;
            uint32_t Af[2][4], Bhf[4][2], Blf[4][2];
#pragma unroll
            for (int mt = 0; mt < 2; ++mt) {
                const uint32_t off = aRow0[mt] + kbyte;
                ldmatrix_x4(Af[mt], bufA + (off ^ ((off >> 3) & 0x70)));
            }
#pragma unroll
            for (int nt = 0; nt < 4; ++nt) {
                const uint32_t off = bRow0[nt] + kbyte;
                const uint32_t so  = off ^ ((off >> 3) & 0x70);
                ldmatrix_x2(Bhf[nt], bufB + so);
                if (TWOB) ldmatrix_x2(Blf[nt], bufB + 16384 + so);
            }
            if (HACC) {
#pragma unroll
                for (int mt = 0; mt < 2; ++mt)
#pragma unroll
                    for (int nt = 0; nt < 4; ++nt)
                        mma16816hh(hacc[mt][nt], Af[mt], Bhf[nt]);
            } else {
#pragma unroll
                for (int mt = 0; mt < 2; ++mt)
#pragma unroll
                    for (int nt = 0; nt < 4; ++nt)
                        mma16816h(acc[mt][nt], Af[mt], Bhf[nt]);
                if (TWOB) {
#pragma unroll
                    for (int mt = 0; mt < 2; ++mt)
#pragma unroll
                        for (int nt = 0; nt < 4; ++nt)
                            mma16816h(acc[mt][nt], Af[mt], Blf[nt]);
                }
            }
        }
        if (HACC) {
            // promote chunk partials to fp32
#pragma unroll
            for (int mt = 0; mt < 2; ++mt)
#pragma unroll
                for (int nt = 0; nt < 4; ++nt) {
                    const __half2 p0 = *(const __half2*)&hacc[mt][nt][0];
                    const __half2 p1 = *(const __half2*)&hacc[mt][nt][1];
                    acc[mt][nt][0] += __low2float(p0);
                    acc[mt][nt][1] += __high2float(p0);
                    acc[mt][nt][2] += __low2float(p1);
                    acc[mt][nt][3] += __high2float(p1);
                }
        }
        __syncthreads();
        if (c + 4 < NCHUNK) issue_chunk(c + 4, buf);
        CP_COMMIT();
    }

#pragma unroll
    for (int mt = 0; mt < 2; ++mt) {
        const int r = m0 + wm * 32 + mt * 16 + (lane >> 2);
#pragma unroll
        for (int nt = 0; nt < 4; ++nt) {
            const int cc = n0 + wn * 32 + nt * 8 + (lane & 3) * 2;
            if (OUT == 0) {
                *(float2*)(C + (size_t)r * LDC + cc)       = make_float2(acc[mt][nt][0], acc[mt][nt][1]);
                *(float2*)(C + (size_t)(r + 8) * LDC + cc) = make_float2(acc[mt][nt][2], acc[mt][nt][3]);
            } else if (OUT == 1) {
                *(uint32_t*)(Oh + (size_t)r * LDC + cc)       = pack_h2(acc[mt][nt][0] * premul, acc[mt][nt][1] * premul);
                *(uint32_t*)(Oh + (size_t)(r + 8) * LDC + cc) = pack_h2(acc[mt][nt][2] * premul, acc[mt][nt][3] * premul);
            } else {
                uint32_t h, l;
                split2h(acc[mt][nt][0] * premul, acc[mt][nt][1] * premul, h, l);
                *(uint32_t*)(Oh + (size_t)r * LDC + cc) = h;
                *(uint32_t*)(Ol + (size_t)r * LDC + cc) = l;
                split2h(acc[mt][nt][2] * premul, acc[mt][nt][3] * premul, h, l);
                *(uint32_t*)(Oh + (size_t)(r + 8) * LDC + cc) = h;
                *(uint32_t*)(Ol + (size_t)(r + 8) * LDC + cc) = l;
            }
        }
    }
}

// ===========================================================================
// FA2-style fp16 HMMA attention: Q single, K/V 2-term (unchanged from R12).
// grid (LQ/128, B_*NH), 256 threads. Emits fp16 single.
// ===========================================================================
#define AQ  0
#define AKH 16384
#define AKL 26624
#define AVH 36864
#define AVL 48128
#define AT_SMEM 59392
#define VT_B 176

__global__ __launch_bounds__(256)
void attn_mma(const __half* __restrict__ Q, const __half* __restrict__ KVh,
              const __half* __restrict__ KVl, __half* __restrict__ Oa)
{
    extern __shared__ char sm[];
    const uint32_t base = smem_u32(sm);
    const int tid  = threadIdx.x;
    const int w    = tid >> 5;
    const int lane = tid & 31;
    const int bh   = blockIdx.y;
    const int b    = bh >> 3;
    const int h    = bh & 7;
    const int qrow0 = b * LQ + blockIdx.x * 128;

    for (int i = tid; i < (AT_SMEM - AVH) / 4; i += 256)
        ((uint32_t*)(sm + AVH))[i] = 0;
    if (tid < 192) {
        const int lvl = tid / 96, rr = (tid % 96) / 32, c = tid % 32;
        *(uint32_t*)(sm + (lvl ? AKL : AKH) + (77 + rr) * 128 + c * 4) = 0;
    }

#pragma unroll
    for (int i = 0; i < 4; ++i) {
        const int idx = i * 256 + tid;
        const int r = idx >> 3, c = idx & 7;
        cp_async16(base + AQ + swz128((uint32_t)(r * 128 + c * 16)),
                   Q + (size_t)(qrow0 + r) * 512 + h * 64 + c * 8);
    }
#pragma unroll
    for (int i = 0; i < 5; ++i) {
        const int idx = i * 256 + tid;
        if (idx < 1232) {
            const int lvl = idx >= 616;
            const int rem = idx - lvl * 616;
            const int j = rem >> 3, c = rem & 7;
            cp_async16(base + (lvl ? AKL : AKH) + swz128((uint32_t)(j * 128 + c * 16)),
                       (lvl ? KVl : KVh) + (size_t)(b * LK + j) * 1024 + h * 64 + c * 8);
        }
    }
    CP_COMMIT();

    for (int idx = tid; idx < 2 * LK * 64; idx += 256) {
        const int lvl = idx >= LK * 64;
        const int rem = idx - lvl * LK * 64;
        const int j = rem >> 6, d = rem & 63;
        const __half v = (lvl ? KVl : KVh)[(size_t)(b * LK + j) * 1024 + 512 + h * 64 + d];
        *(__half*)(sm + (lvl ? AVL : AVH) + d * VT_B + j * 2) = v;
    }
    CP_WAIT0();
    __syncthreads();

    float s[10][4];
#pragma unroll
    for (int nt = 0; nt < 10; ++nt)
#pragma unroll
        for (int q = 0; q < 4; ++q) s[nt][q] = 0.f;

    const uint32_t aBase = (uint32_t)((w * 16 + (lane & 15)) * 128 + (lane >> 4) * 16);
    const uint32_t bRowK = (uint32_t)(((lane & 7)) * 128 + ((lane >> 3) & 1) * 16);
#pragma unroll
    for (int kb = 0; kb < 4; ++kb) {
        const uint32_t ao = aBase + kb * 32;
        uint32_t qf[4];
        ldmatrix_x4(qf, base + AQ + (ao ^ ((ao >> 3) & 0x70)));
#pragma unroll
        for (int nt = 0; nt < 10; ++nt) {
            const uint32_t bo = bRowK + nt * 8 * 128 + kb * 32;
            const uint32_t bso = bo ^ ((bo >> 3) & 0x70);
            uint32_t khf[2], klf[2];
            ldmatrix_x2(khf, base + AKH + bso);
            ldmatrix_x2(klf, base + AKL + bso);
            mma16816h(s[nt], qf, khf);
            mma16816h(s[nt], qf, klf);
        }
    }

    const int t = lane & 3;
    if (t == 2) { s[9][1] = -1e30f; s[9][3] = -1e30f; }
    if (t == 3) { s[9][0] = -1e30f; s[9][1] = -1e30f; s[9][2] = -1e30f; s[9][3] = -1e30f; }

    float mlo = -1e30f, mhi = -1e30f;
#pragma unroll
    for (int nt = 0; nt < 10; ++nt) {
        mlo = fmaxf(mlo, fmaxf(s[nt][0], s[nt][1]));
        mhi = fmaxf(mhi, fmaxf(s[nt][2], s[nt][3]));
    }
#pragma unroll
    for (int o = 1; o <= 2; o <<= 1) {
        mlo = fmaxf(mlo, __shfl_xor_sync(0xffffffffu, mlo, o));
        mhi = fmaxf(mhi, __shfl_xor_sync(0xffffffffu, mhi, o));
    }
    float slo = 0.f, shi = 0.f;
#pragma unroll
    for (int nt = 0; nt < 10; ++nt) {
        s[nt][0] = __expf(s[nt][0] - mlo);
        s[nt][1] = __expf(s[nt][1] - mlo);
        s[nt][2] = __expf(s[nt][2] - mhi);
        s[nt][3] = __expf(s[nt][3] - mhi);
        slo += s[nt][0] + s[nt][1];
        shi += s[nt][2] + s[nt][3];
    }
#pragma unroll
    for (int o = 1; o <= 2; o <<= 1) {
        slo += __shfl_xor_sync(0xffffffffu, slo, o);
        shi += __shfl_xor_sync(0xffffffffu, shi, o);
    }
    const float rlo = 1.f / slo, rhi = 1.f / shi;

    float o[8][4];
#pragma unroll
    for (int dn = 0; dn < 8; ++dn)
#pragma unroll
        for (int q = 0; q < 4; ++q) o[dn][q] = 0.f;

    const uint32_t bRowV = (uint32_t)(((lane & 7)) * VT_B + ((lane >> 3) & 1) * 16);
#pragma unroll
    for (int kt = 0; kt < 5; ++kt) {
        uint32_t p[4];
        p[0] = pack_h2(s[2 * kt][0],     s[2 * kt][1]);
        p[1] = pack_h2(s[2 * kt][2],     s[2 * kt][3]);
        p[2] = pack_h2(s[2 * kt + 1][0], s[2 * kt + 1][1]);
        p[3] = pack_h2(s[2 * kt + 1][2], s[2 * kt + 1][3]);
#pragma unroll
        for (int dn = 0; dn < 8; ++dn) {
            const uint32_t bo = bRowV + dn * 8 * VT_B + kt * 32;
            uint32_t vhf[2], vlf[2];
            ldmatrix_x2(vhf, base + AVH + bo);
            ldmatrix_x2(vlf, base + AVL + bo);
            mma16816h(o[dn], p, vhf);
            mma16816h(o[dn], p, vlf);
        }
    }

    const int g = lane >> 2;
    const size_t rA = (size_t)(qrow0 + w * 16 + g) * 512 + h * 64;
    const size_t rB = rA + 8 * 512;
#pragma unroll
    for (int dn = 0; dn < 8; ++dn) {
        const int col = dn * 8 + 2 * t;
        *(uint32_t*)(Oa + rA + col) = pack_h2(o[dn][0] * rlo, o[dn][1] * rlo);
        *(uint32_t*)(Oa + rB + col) = pack_h2(o[dn][2] * rhi, o[dn][3] * rhi);
    }
}

// ===========================================================================
extern "C" void kernel_launch(void* const* d_in, const int* in_sizes, int n_in,
                              void* d_out, int out_size)
{
    (void)in_sizes; (void)n_in; (void)out_size;
    const float* x    = (const float*)d_in[0];
    const float* cond = (const float*)d_in[1];
    const float* w_q  = (const float*)d_in[2];
    const float* w_k  = (const float*)d_in[3];
    const float* w_v  = (const float*)d_in[4];
    const float* w_o  = (const float*)d_in[5];
    float* out = (float*)d_out;

    __half *xh, *ch, *ah, *qh, *wqh, *woh, *wkvh, *wkvl, *kvh, *kvl;
    cudaGetSymbolAddress((void**)&xh, g_xh);
    cudaGetSymbolAddress((void**)&ch, g_ch);
    cudaGetSymbolAddress((void**)&ah, g_ah);
    cudaGetSymbolAddress((void**)&qh, g_qh);
    cudaGetSymbolAddress((void**)&wqh, g_wqh);
    cudaGetSymbolAddress((void**)&woh, g_woh);
    cudaGetSymbolAddress((void**)&wkvh, g_wkvh); cudaGetSymbolAddress((void**)&wkvl, g_wkvl);
    cudaGetSymbolAddress((void**)&kvh, g_kvh);   cudaGetSymbolAddress((void**)&kvl, g_kvl);

    cudaFuncSetAttribute((void*)gemm_f16<512, 512, 1, false, true>,  cudaFuncAttributeMaxDynamicSharedMemorySize, SM_1B);
    cudaFuncSetAttribute((void*)gemm_f16<512, 512, 0, false, true>,  cudaFuncAttributeMaxDynamicSharedMemorySize, SM_1B);
    cudaFuncSetAttribute((void*)gemm_f16<768, 1024, 2, true, false>, cudaFuncAttributeMaxDynamicSharedMemorySize, SM_2B);
    cudaFuncSetAttribute((void*)attn_mma, cudaFuncAttributeMaxDynamicSharedMemorySize, AT_SMEM);

    const int XN4 = B_ * LQ * DMODEL / 4;
    const int WN4 = DMODEL * INNER / 4;
    const int CN4 = MKV * DCOND / 4;
    const int WKN4 = INNER * DCOND / 4;
    cvt_h<<<(XN4 + 255) / 256, 256>>>((const float4*)x, (uint2*)xh, XN4);
    cvt_h<<<(CN4 + 255) / 256, 256>>>((const float4*)cond, (uint2*)ch, CN4);
    cvt_h<<<(WN4 + 255) / 256, 256>>>((const float4*)w_q, (uint2*)wqh, WN4);
    cvt_h<<<(WN4 + 255) / 256, 256>>>((const float4*)w_o, (uint2*)woh, WN4);
    cvt_h2<<<(WKN4 + 255) / 256, 256>>>((const float4*)w_k, (uint2*)wkvh, (uint2*)wkvl, WKN4);
    cvt_h2<<<(WKN4 + 255) / 256, 256>>>((const float4*)w_v,
        (uint2*)(wkvh + (size_t)INNER * DCOND), (uint2*)(wkvl + (size_t)INNER * DCOND), WKN4);

    // K+V projection (2-term B, fp32 accum) -> fp16 hi/lo [MKVP,1024]
    gemm_f16<768, 1024, 2, true, false><<<dim3(MKVP / 128, 8), 512, SM_2B>>>(
        ch, wkvh, wkvl, nullptr, kvh, kvl, 1.f);

    // Q projection: fp16 A cp.async, fp16 accum (rate test), pre-scaled 0.125
    gemm_f16<512, 512, 1, false, true><<<dim3(512, 4), 512, SM_1B>>>(
        xh, wqh, nullptr, nullptr, qh, nullptr, 0.125f);

    // fp16 tensor-core attention -> fp16 single
    attn_mma<<<dim3(LQ / 128, B_ * NH), 256, AT_SMEM>>>(qh, kvh, kvl, ah);

    // Output projection: fp16 accum (rate test) -> fp32
    gemm_f16<512, 512, 0, false, true><<<dim3(512, 4), 512, SM_1B>>>(
        ah, woh, nullptr, out, nullptr, nullptr, 1.f);
}

// round 14
// speedup vs baseline: 5.8833x; 1.1219x over previous
#include <cuda_runtime.h>
#include <cuda_fp16.h>
#include <cstdint>
#include <math.h>

#define B_     16
#define LQ     4096
#define LK     77
#define DMODEL 512
#define DCOND  768
#define NH     8
#define HD     64
#define INNER  512   // NH*HD
#define MKV    1232  // B_*LK
#define MKVP   1280  // padded to 128

// Scratch (allocation-free rule: __device__ globals; zero-initialized)
__device__ __half g_xh[(size_t)B_ * LQ * DMODEL];     // x fp16
__device__ __half g_ch[MKVP * DCOND];                 // cond fp16 (pad rows 0)
__device__ __half g_ah[(size_t)B_ * LQ * INNER];      // attention out fp16
__device__ __half g_qh[(size_t)B_ * LQ * INNER];      // Q*0.125 fp16 single
__device__ __half g_wqh[DMODEL * INNER];              // w_q single fp16
__device__ __half g_woh[DMODEL * INNER];              // w_o single fp16
__device__ __half g_wkvh[2 * INNER * DCOND];          // [w_k ; w_v] 2-term
__device__ __half g_wkvl[2 * INNER * DCOND];
__device__ __half g_kvh[(size_t)MKVP * 1024];         // K cols 0..511, V 512..1023
__device__ __half g_kvl[(size_t)MKVP * 1024];         // fp16 residuals

// ===========================================================================
// Helpers (base PTX only)
// ===========================================================================
__device__ __forceinline__ uint32_t smem_u32(const void* p) {
    uint32_t a;
    asm("{ .reg .u64 t; cvta.to.shared.u64 t, %1; cvt.u32.u64 %0, t; }" : "=r"(a) : "l"(p));
    return a;
}
__device__ __forceinline__ uint32_t swz128(uint32_t off) { return off ^ ((off >> 3) & 0x70); }

__device__ __forceinline__ void ldmatrix_x4(uint32_t* r, uint32_t addr) {
    asm volatile("ldmatrix.sync.aligned.m8n8.x4.shared.b16 {%0,%1,%2,%3}, [%4];"
        : "=r"(r[0]), "=r"(r[1]), "=r"(r[2]), "=r"(r[3]) : "r"(addr));
}
__device__ __forceinline__ void ldmatrix_x2(uint32_t* r, uint32_t addr) {
    asm volatile("ldmatrix.sync.aligned.m8n8.x2.shared.b16 {%0,%1}, [%2];"
        : "=r"(r[0]), "=r"(r[1]) : "r"(addr));
}
// fp16 MMA, fp32 accum
__device__ __forceinline__ void mma16816h(float* d, const uint32_t* a, const uint32_t* b) {
    asm volatile("mma.sync.aligned.m16n8k16.row.col.f32.f16.f16.f32 "
        "{%0,%1,%2,%3}, {%4,%5,%6,%7}, {%8,%9}, {%0,%1,%2,%3};"
        : "+f"(d[0]), "+f"(d[1]), "+f"(d[2]), "+f"(d[3])
        : "r"(a[0]), "r"(a[1]), "r"(a[2]), "r"(a[3]), "r"(b[0]), "r"(b[1]));
}
__device__ __forceinline__ void cp_async16(uint32_t dst, const void* src) {
    asm volatile("cp.async.cg.shared.global [%0], [%1], 16;" :: "r"(dst), "l"(src));
}
#define CP_COMMIT() asm volatile("cp.async.commit_group;" ::: "memory")
#define CP_WAIT3()  asm volatile("cp.async.wait_group 3;" ::: "memory")
#define CP_WAIT0()  asm volatile("cp.async.wait_group 0;" ::: "memory")

__device__ __forceinline__ uint32_t pack_h2(float x, float y) {
    __half2 h = __floats2half2_rn(x, y);
    return *(const uint32_t*)&h;
}
__device__ __forceinline__ void split2h(float x, float y, uint32_t& hi, uint32_t& lo) {
    const __half hx = __float2half_rn(x), hy = __float2half_rn(y);
    hi = (uint32_t)__half_as_ushort(hx) | ((uint32_t)__half_as_ushort(hy) << 16);
    lo = pack_h2(x - __half2float(hx), y - __half2float(hy));
}

// fp32 -> single fp16
__global__ void cvt_h(const float4* __restrict__ in, uint2* __restrict__ out, int n4)
{
    const int i = blockIdx.x * blockDim.x + threadIdx.x;
    if (i >= n4) return;
    const float4 v = in[i];
    out[i] = make_uint2(pack_h2(v.x, v.y), pack_h2(v.z, v.w));
}
// fp32 -> fp16 hi + residual lo
__global__ void cvt_h2(const float4* __restrict__ in, uint2* __restrict__ hi,
                       uint2* __restrict__ lo, int n4)
{
    const int i = blockIdx.x * blockDim.x + threadIdx.x;
    if (i >= n4) return;
    const float4 v = in[i];
    uint32_t h0, l0, h1, l1;
    split2h(v.x, v.y, h0, l0);
    split2h(v.z, v.w, h1, l1);
    hi[i] = make_uint2(h0, h1);
    lo[i] = make_uint2(l0, l1);
}

// ===========================================================================
// Narrow-tile fp16 GEMM (single B): 128x64 tile, K-chunk 64, 4-stage cp.async,
// 256 thr (8 warps, 4m x 2n), warp tile 32x32. 24KB/stage -> 96KB -> 2 CTA/SM
// (syncs/waits in one CTA hide under the other's MMA stream).
// OUT: 0 = fp32 C; 1 = fp16 single (premul).
// ===========================================================================
#define SM_N (4 * 24576)

template <int KDIM, int LDC, int OUT>
__global__ void __launch_bounds__(256, 2)
gemm_n(const __half* __restrict__ A, const __half* __restrict__ Bw,
       float* __restrict__ C, __half* __restrict__ Oh, float premul)
{
    constexpr int NCHUNK = KDIM / 64;
    extern __shared__ char sm[];
    const uint32_t base = smem_u32(sm);
    const int tid  = threadIdx.x;
    const int wid  = tid >> 5;
    const int lane = tid & 31;
    const int wm   = wid & 3;    // 4 m-blocks of 32
    const int wn   = wid >> 2;   // 2 n-blocks of 32

    const int m0 = blockIdx.x * 128;
    const int n0 = blockIdx.y * 64;
    const __half* A0 = A  + (size_t)m0 * KDIM;
    const __half* B0 = Bw + (size_t)n0 * KDIM;

    float acc[2][4][4];
#pragma unroll
    for (int mt = 0; mt < 2; ++mt)
#pragma unroll
        for (int nt = 0; nt < 4; ++nt)
#pragma unroll
            for (int q = 0; q < 4; ++q) acc[mt][nt][q] = 0.f;

    uint32_t aRow0[2], bRow0[4];
#pragma unroll
    for (int mt = 0; mt < 2; ++mt)
        aRow0[mt] = (uint32_t)((wm * 32 + mt * 16 + (lane & 15)) * 128 + (lane >> 4) * 16);
#pragma unroll
    for (int nt = 0; nt < 4; ++nt)
        bRow0[nt] = (uint32_t)((wn * 32 + nt * 8 + (lane & 7)) * 128 + ((lane >> 3) & 1) * 16);

    // stage: A 1024 16B-chunks + B 512 -> 4 + 2 per thread
    auto issue_chunk = [&](int c, int buf) {
        const int kc = c * 64;
        const uint32_t tb = base + buf * 24576;
#pragma unroll
        for (int i = 0; i < 4; ++i) {
            const int idx = i * 256 + tid;          // 0..1023
            const int row = idx >> 3, c8 = idx & 7;
            cp_async16(tb + swz128((uint32_t)(row * 128 + c8 * 16)),
                       A0 + (size_t)row * KDIM + kc + c8 * 8);
        }
#pragma unroll
        for (int i = 0; i < 2; ++i) {
            const int idx = i * 256 + tid;          // 0..511
            const int row = idx >> 3, c8 = idx & 7;
            cp_async16(tb + 16384 + swz128((uint32_t)(row * 128 + c8 * 16)),
                       B0 + (size_t)row * KDIM + kc + c8 * 8);
        }
    };

    issue_chunk(0, 0); CP_COMMIT();
    issue_chunk(1, 1); CP_COMMIT();
    issue_chunk(2, 2); CP_COMMIT();
    issue_chunk(3, 3); CP_COMMIT();

    for (int c = 0; c < NCHUNK; ++c) {
        const int buf = c & 3;
        CP_WAIT3();
        __syncthreads();

        const uint32_t bufA = base + buf * 24576;
        const uint32_t bufB = bufA + 16384;
#pragma unroll
        for (int kb = 0; kb < 4; ++kb) {
            const uint32_t kbyte = kb * 32;
            uint32_t Af[2][4], Bf[4][2];
#pragma unroll
            for (int mt = 0; mt < 2; ++mt) {
                const uint32_t off = aRow0[mt] + kbyte;
                ldmatrix_x4(Af[mt], bufA + (off ^ ((off >> 3) & 0x70)));
            }
#pragma unroll
            for (int nt = 0; nt < 4; ++nt) {
                const uint32_t off = bRow0[nt] + kbyte;
                ldmatrix_x2(Bf[nt], bufB + (off ^ ((off >> 3) & 0x70)));
            }
#pragma unroll
            for (int mt = 0; mt < 2; ++mt)
#pragma unroll
                for (int nt = 0; nt < 4; ++nt)
                    mma16816h(acc[mt][nt], Af[mt], Bf[nt]);
        }
        __syncthreads();
        if (c + 4 < NCHUNK) issue_chunk(c + 4, buf);
        CP_COMMIT();
    }

#pragma unroll
    for (int mt = 0; mt < 2; ++mt) {
        const int r = m0 + wm * 32 + mt * 16 + (lane >> 2);
#pragma unroll
        for (int nt = 0; nt < 4; ++nt) {
            const int cc = n0 + wn * 32 + nt * 8 + (lane & 3) * 2;
            if (OUT == 0) {
                *(float2*)(C + (size_t)r * LDC + cc)       = make_float2(acc[mt][nt][0], acc[mt][nt][1]);
                *(float2*)(C + (size_t)(r + 8) * LDC + cc) = make_float2(acc[mt][nt][2], acc[mt][nt][3]);
            } else {
                *(uint32_t*)(Oh + (size_t)r * LDC + cc)       = pack_h2(acc[mt][nt][0] * premul, acc[mt][nt][1] * premul);
                *(uint32_t*)(Oh + (size_t)(r + 8) * LDC + cc) = pack_h2(acc[mt][nt][2] * premul, acc[mt][nt][3] * premul);
            }
        }
    }
}

// ===========================================================================
// KV projection GEMM (2-term B, fp16 hi/lo split output), 128x128 tile,
// 512 thr, 4-stage — unchanged from R12 (small, not worth retuning).
// ===========================================================================
#define SM_KV (4 * 49152)

__global__ void __launch_bounds__(512, 1)
gemm_kv(const __half* __restrict__ A, const __half* __restrict__ Bh,
        const __half* __restrict__ Bl, __half* __restrict__ Oh, __half* __restrict__ Ol)
{
    constexpr int KDIM = DCOND, LDC = 1024, NCHUNK = KDIM / 64;
    extern __shared__ char sm[];
    const uint32_t base = smem_u32(sm);
    const int tid  = threadIdx.x;
    const int wid  = tid >> 5;
    const int lane = tid & 31;
    const int wm   = wid & 3;
    const int wn   = wid >> 2;

    const int m0 = blockIdx.x * 128;
    const int n0 = blockIdx.y * 128;
    const __half* A0  = A + (size_t)m0 * KDIM;
    const __half* Bh0 = Bh + (size_t)n0 * KDIM;
    const __half* Bl0 = Bl + (size_t)n0 * KDIM;

    float acc[2][4][4];
#pragma unroll
    for (int mt = 0; mt < 2; ++mt)
#pragma unroll
        for (int nt = 0; nt < 4; ++nt)
#pragma unroll
            for (int q = 0; q < 4; ++q) acc[mt][nt][q] = 0.f;

    uint32_t aRow0[2], bRow0[4];
#pragma unroll
    for (int mt = 0; mt < 2; ++mt)
        aRow0[mt] = (uint32_t)((wm * 32 + mt * 16 + (lane & 15)) * 128 + (lane >> 4) * 16);
#pragma unroll
    for (int nt = 0; nt < 4; ++nt)
        bRow0[nt] = (uint32_t)((wn * 32 + nt * 8 + (lane & 7)) * 128 + ((lane >> 3) & 1) * 16);

    auto issue_chunk = [&](int c, int buf) {
        const int kc = c * 64;
        const uint32_t tb = base + buf * 49152;
#pragma unroll
        for (int i = 0; i < 2; ++i) {
            const int idx = i * 512 + tid;
            const int row = idx >> 3, c8 = idx & 7;
            const uint32_t so = swz128((uint32_t)(row * 128 + c8 * 16));
            const size_t go = (size_t)row * KDIM + kc + c8 * 8;
            cp_async16(tb + so,         A0  + go);
            cp_async16(tb + 16384 + so, Bh0 + go);
            cp_async16(tb + 32768 + so, Bl0 + go);
        }
    };

    issue_chunk(0, 0); CP_COMMIT();
    issue_chunk(1, 1); CP_COMMIT();
    issue_chunk(2, 2); CP_COMMIT();
    issue_chunk(3, 3); CP_COMMIT();

    for (int c = 0; c < NCHUNK; ++c) {
        const int buf = c & 3;
        CP_WAIT3();
        __syncthreads();
        const uint32_t bufA = base + buf * 49152;
        const uint32_t bufB = bufA + 16384;
#pragma unroll
        for (int kb = 0; kb < 4; ++kb) {
            const uint32_t kbyte = kb * 32;
            uint32_t Af[2][4], Bhf[4][2], Blf[4][2];
#pragma unroll
            for (int mt = 0; mt < 2; ++mt) {
                const uint32_t off = aRow0[mt] + kbyte;
                ldmatrix_x4(Af[mt], bufA + (off ^ ((off >> 3) & 0x70)));
            }
#pragma unroll
            for (int nt = 0; nt < 4; ++nt) {
                const uint32_t off = bRow0[nt] + kbyte;
                const uint32_t so  = off ^ ((off >> 3) & 0x70);
                ldmatrix_x2(Bhf[nt], bufB + so);
                ldmatrix_x2(Blf[nt], bufB + 16384 + so);
            }
#pragma unroll
            for (int mt = 0; mt < 2; ++mt)
#pragma unroll
                for (int nt = 0; nt < 4; ++nt)
                    mma16816h(acc[mt][nt], Af[mt], Bhf[nt]);
#pragma unroll
            for (int mt = 0; mt < 2; ++mt)
#pragma unroll
                for (int nt = 0; nt < 4; ++nt)
                    mma16816h(acc[mt][nt], Af[mt], Blf[nt]);
        }
        __syncthreads();
        if (c + 4 < NCHUNK) issue_chunk(c + 4, buf);
        CP_COMMIT();
    }

#pragma unroll
    for (int mt = 0; mt < 2; ++mt) {
        const int r = m0 + wm * 32 + mt * 16 + (lane >> 2);
#pragma unroll
        for (int nt = 0; nt < 4; ++nt) {
            const int cc = n0 + wn * 32 + nt * 8 + (lane & 3) * 2;
            uint32_t h, l;
            split2h(acc[mt][nt][0], acc[mt][nt][1], h, l);
            *(uint32_t*)(Oh + (size_t)r * LDC + cc) = h;
            *(uint32_t*)(Ol + (size_t)r * LDC + cc) = l;
            split2h(acc[mt][nt][2], acc[mt][nt][3], h, l);
            *(uint32_t*)(Oh + (size_t)(r + 8) * LDC + cc) = h;
            *(uint32_t*)(Ol + (size_t)(r + 8) * LDC + cc) = l;
        }
    }
}

// ===========================================================================
// FA2-style fp16 HMMA attention: Q single, K/V 2-term (unchanged from R12).
// grid (LQ/128, B_*NH), 256 threads. Emits fp16 single.
// ===========================================================================
#define AQ  0
#define AKH 16384
#define AKL 26624
#define AVH 36864
#define AVL 48128
#define AT_SMEM 59392
#define VT_B 176

__global__ __launch_bounds__(256)
void attn_mma(const __half* __restrict__ Q, const __half* __restrict__ KVh,
              const __half* __restrict__ KVl, __half* __restrict__ Oa)
{
    extern __shared__ char sm[];
    const uint32_t base = smem_u32(sm);
    const int tid  = threadIdx.x;
    const int w    = tid >> 5;
    const int lane = tid & 31;
    const int bh   = blockIdx.y;
    const int b    = bh >> 3;
    const int h    = bh & 7;
    const int qrow0 = b * LQ + blockIdx.x * 128;

    for (int i = tid; i < (AT_SMEM - AVH) / 4; i += 256)
        ((uint32_t*)(sm + AVH))[i] = 0;
    if (tid < 192) {
        const int lvl = tid / 96, rr = (tid % 96) / 32, c = tid % 32;
        *(uint32_t*)(sm + (lvl ? AKL : AKH) + (77 + rr) * 128 + c * 4) = 0;
    }

#pragma unroll
    for (int i = 0; i < 4; ++i) {
        const int idx = i * 256 + tid;
        const int r = idx >> 3, c = idx & 7;
        cp_async16(base + AQ + swz128((uint32_t)(r * 128 + c * 16)),
                   Q + (size_t)(qrow0 + r) * 512 + h * 64 + c * 8);
    }
#pragma unroll
    for (int i = 0; i < 5; ++i) {
        const int idx = i * 256 + tid;
        if (idx < 1232) {
            const int lvl = idx >= 616;
            const int rem = idx - lvl * 616;
            const int j = rem >> 3, c = rem & 7;
            cp_async16(base + (lvl ? AKL : AKH) + swz128((uint32_t)(j * 128 + c * 16)),
                       (lvl ? KVl : KVh) + (size_t)(b * LK + j) * 1024 + h * 64 + c * 8);
        }
    }
    CP_COMMIT();

    for (int idx = tid; idx < 2 * LK * 64; idx += 256) {
        const int lvl = idx >= LK * 64;
        const int rem = idx - lvl * LK * 64;
        const int j = rem >> 6, d = rem & 63;
        const __half v = (lvl ? KVl : KVh)[(size_t)(b * LK + j) * 1024 + 512 + h * 64 + d];
        *(__half*)(sm + (lvl ? AVL : AVH) + d * VT_B + j * 2) = v;
    }
    CP_WAIT0();
    __syncthreads();

    float s[10][4];
#pragma unroll
    for (int nt = 0; nt < 10; ++nt)
#pragma unroll
        for (int q = 0; q < 4; ++q) s[nt][q] = 0.f;

    const uint32_t aBase = (uint32_t)((w * 16 + (lane & 15)) * 128 + (lane >> 4) * 16);
    const uint32_t bRowK = (uint32_t)(((lane & 7)) * 128 + ((lane >> 3) & 1) * 16);
#pragma unroll
    for (int kb = 0; kb < 4; ++kb) {
        const uint32_t ao = aBase + kb * 32;
        uint32_t qf[4];
        ldmatrix_x4(qf, base + AQ + (ao ^ ((ao >> 3) & 0x70)));
#pragma unroll
        for (int nt = 0; nt < 10; ++nt) {
            const uint32_t bo = bRowK + nt * 8 * 128 + kb * 32;
            const uint32_t bso = bo ^ ((bo >> 3) & 0x70);
            uint32_t khf[2], klf[2];
            ldmatrix_x2(khf, base + AKH + bso);
            ldmatrix_x2(klf, base + AKL + bso);
            mma16816h(s[nt], qf, khf);
            mma16816h(s[nt], qf, klf);
        }
    }

    const int t = lane & 3;
    if (t == 2) { s[9][1] = -1e30f; s[9][3] = -1e30f; }
    if (t == 3) { s[9][0] = -1e30f; s[9][1] = -1e30f; s[9][2] = -1e30f; s[9][3] = -1e30f; }

    float mlo = -1e30f, mhi = -1e30f;
#pragma unroll
    for (int nt = 0; nt < 10; ++nt) {
        mlo = fmaxf(mlo, fmaxf(s[nt][0], s[nt][1]));
        mhi = fmaxf(mhi, fmaxf(s[nt][2], s[nt][3]));
    }
#pragma unroll
    for (int o = 1; o <= 2; o <<= 1) {
        mlo = fmaxf(mlo, __shfl_xor_sync(0xffffffffu, mlo, o));
        mhi = fmaxf(mhi, __shfl_xor_sync(0xffffffffu, mhi, o));
    }
    float slo = 0.f, shi = 0.f;
#pragma unroll
    for (int nt = 0; nt < 10; ++nt) {
        s[nt][0] = __expf(s[nt][0] - mlo);
        s[nt][1] = __expf(s[nt][1] - mlo);
        s[nt][2] = __expf(s[nt][2] - mhi);
        s[nt][3] = __expf(s[nt][3] - mhi);
        slo += s[nt][0] + s[nt][1];
        shi += s[nt][2] + s[nt][3];
    }
#pragma unroll
    for (int o = 1; o <= 2; o <<= 1) {
        slo += __shfl_xor_sync(0xffffffffu, slo, o);
        shi += __shfl_xor_sync(0xffffffffu, shi, o);
    }
    const float rlo = 1.f / slo, rhi = 1.f / shi;

    float o[8][4];
#pragma unroll
    for (int dn = 0; dn < 8; ++dn)
#pragma unroll
        for (int q = 0; q < 4; ++q) o[dn][q] = 0.f;

    const uint32_t bRowV = (uint32_t)(((lane & 7)) * VT_B + ((lane >> 3) & 1) * 16);
#pragma unroll
    for (int kt = 0; kt < 5; ++kt) {
        uint32_t p[4];
        p[0] = pack_h2(s[2 * kt][0],     s[2 * kt][1]);
        p[1] = pack_h2(s[2 * kt][2],     s[2 * kt][3]);
        p[2] = pack_h2(s[2 * kt + 1][0], s[2 * kt + 1][1]);
        p[3] = pack_h2(s[2 * kt + 1][2], s[2 * kt + 1][3]);
#pragma unroll
        for (int dn = 0; dn < 8; ++dn) {
            const uint32_t bo = bRowV + dn * 8 * VT_B + kt * 32;
            uint32_t vhf[2], vlf[2];
            ldmatrix_x2(vhf, base + AVH + bo);
            ldmatrix_x2(vlf, base + AVL + bo);
            mma16816h(o[dn], p, vhf);
            mma16816h(o[dn], p, vlf);
        }
    }

    const int g = lane >> 2;
    const size_t rA = (size_t)(qrow0 + w * 16 + g) * 512 + h * 64;
    const size_t rB = rA + 8 * 512;
#pragma unroll
    for (int dn = 0; dn < 8; ++dn) {
        const int col = dn * 8 + 2 * t;
        *(uint32_t*)(Oa + rA + col) = pack_h2(o[dn][0] * rlo, o[dn][1] * rlo);
        *(uint32_t*)(Oa + rB + col) = pack_h2(o[dn][2] * rhi, o[dn][3] * rhi);
    }
}

// ===========================================================================
extern "C" void kernel_launch(void* const* d_in, const int* in_sizes, int n_in,
                              void* d_out, int out_size)
{
    (void)in_sizes; (void)n_in; (void)out_size;
    const float* x    = (const float*)d_in[0];
    const float* cond = (const float*)d_in[1];
    const float* w_q  = (const float*)d_in[2];
    const float* w_k  = (const float*)d_in[3];
    const float* w_v  = (const float*)d_in[4];
    const float* w_o  = (const float*)d_in[5];
    float* out = (float*)d_out;

    __half *xh, *ch, *ah, *qh, *wqh, *woh, *wkvh, *wkvl, *kvh, *kvl;
    cudaGetSymbolAddress((void**)&xh, g_xh);
    cudaGetSymbolAddress((void**)&ch, g_ch);
    cudaGetSymbolAddress((void**)&ah, g_ah);
    cudaGetSymbolAddress((void**)&qh, g_qh);
    cudaGetSymbolAddress((void**)&wqh, g_wqh);
    cudaGetSymbolAddress((void**)&woh, g_woh);
    cudaGetSymbolAddress((void**)&wkvh, g_wkvh); cudaGetSymbolAddress((void**)&wkvl, g_wkvl);
    cudaGetSymbolAddress((void**)&kvh, g_kvh);   cudaGetSymbolAddress((void**)&kvl, g_kvl);

    cudaFuncSetAttribute((void*)gemm_n<512, 512, 1>, cudaFuncAttributeMaxDynamicSharedMemorySize, SM_N);
    cudaFuncSetAttribute((void*)gemm_n<512, 512, 0>, cudaFuncAttributeMaxDynamicSharedMemorySize, SM_N);
    cudaFuncSetAttribute((void*)gemm_kv, cudaFuncAttributeMaxDynamicSharedMemorySize, SM_KV);
    cudaFuncSetAttribute((void*)attn_mma, cudaFuncAttributeMaxDynamicSharedMemorySize, AT_SMEM);

    const int XN4 = B_ * LQ * DMODEL / 4;
    const int WN4 = DMODEL * INNER / 4;
    const int CN4 = MKV * DCOND / 4;
    const int WKN4 = INNER * DCOND / 4;
    cvt_h<<<(XN4 + 255) / 256, 256>>>((const float4*)x, (uint2*)xh, XN4);
    cvt_h<<<(CN4 + 255) / 256, 256>>>((const float4*)cond, (uint2*)ch, CN4);
    cvt_h<<<(WN4 + 255) / 256, 256>>>((const float4*)w_q, (uint2*)wqh, WN4);
    cvt_h<<<(WN4 + 255) / 256, 256>>>((const float4*)w_o, (uint2*)woh, WN4);
    cvt_h2<<<(WKN4 + 255) / 256, 256>>>((const float4*)w_k, (uint2*)wkvh, (uint2*)wkvl, WKN4);
    cvt_h2<<<(WKN4 + 255) / 256, 256>>>((const float4*)w_v,
        (uint2*)(wkvh + (size_t)INNER * DCOND), (uint2*)(wkvl + (size_t)INNER * DCOND), WKN4);

    // K+V projection (2-term B, fp32 accum) -> fp16 hi/lo [MKVP,1024]
    gemm_kv<<<dim3(MKVP / 128, 8), 512, SM_KV>>>(ch, wkvh, wkvl, kvh, kvl);

    // Q projection: 128x64 tiles, 2 CTA/SM; fp16 out pre-scaled 0.125
    gemm_n<512, 512, 1><<<dim3(512, 8), 256, SM_N>>>(xh, wqh, nullptr, qh, 0.125f);

    // fp16 tensor-core attention -> fp16 single
    attn_mma<<<dim3(LQ / 128, B_ * NH), 256, AT_SMEM>>>(qh, kvh, kvl, ah);

    // Output projection: 128x64 tiles, 2 CTA/SM -> fp32
    gemm_n<512, 512, 0><<<dim3(512, 8), 256, SM_N>>>(ah, woh, out, nullptr, 1.f);
}